// round 14
// baseline (speedup 1.0000x reference)
#include <cuda_runtime.h>
#include <cuda_fp16.h>
#include <cstdint>

#define NB 16
#define NP 8192
#define NG 512
#define NK 32
#define TOK 384
#define NM (NB*NG)          // 8192 groups
#define MTOT (NM*NK)        // 262144 rows

#define NEG_INF __int_as_float(0xff800000)

typedef unsigned long long ull;

// ===================== global scratch =====================
__device__ __align__(16) __half F1h[(size_t)MTOT*128];
__device__ __align__(16) __half F1l[(size_t)MTOT*128];
__device__ __align__(16) __half F2q[(size_t)MTOT*256];
__device__ __align__(16) __half F3q[(size_t)MTOT*512];
__device__ __align__(16) __half GMq[(size_t)NM*256];
__device__ __align__(16) float  G3[(size_t)NM*512];
__device__ __align__(16) __half W2q[256*128];
__device__ __align__(16) __half W3gq[512*256];
__device__ __align__(16) __half W3fq[512*256];
__device__ __align__(16) __half W4q[384*512];

// ===================== helpers =====================
__device__ __forceinline__ uint32_t smem_u32(const void* p) {
    uint32_t a;
    asm("{ .reg .u64 t; cvta.to.shared.u64 t, %1; cvt.u32.u64 %0, t; }" : "=r"(a) : "l"(p));
    return a;
}
__device__ __forceinline__ uint32_t swz64(uint32_t o)  { return o ^ ((o >> 3) & 0x30); }
__device__ __forceinline__ uint32_t swz128(uint32_t o) { return o ^ ((o >> 3) & 0x70); }

__device__ __forceinline__ void cp16(uint32_t d, const void* s) {
    asm volatile("cp.async.cg.shared.global [%0], [%1], 16;" :: "r"(d), "l"(s));
}
__device__ __forceinline__ void ldsm4(uint32_t* r, uint32_t addr) {
    asm volatile("ldmatrix.sync.aligned.m8n8.x4.shared.b16 {%0,%1,%2,%3}, [%4];"
        : "=r"(r[0]), "=r"(r[1]), "=r"(r[2]), "=r"(r[3]) : "r"(addr));
}
__device__ __forceinline__ void mma16816(float* d, const uint32_t* a, const uint32_t* b) {
    asm volatile("mma.sync.aligned.m16n8k16.row.col.f32.f16.f16.f32 "
        "{%0,%1,%2,%3}, {%4,%5,%6,%7}, {%8,%9}, {%0,%1,%2,%3};"
        : "+f"(d[0]), "+f"(d[1]), "+f"(d[2]), "+f"(d[3])
        : "r"(a[0]), "r"(a[1]), "r"(a[2]), "r"(a[3]), "r"(b[0]), "r"(b[1]));
}
__device__ __forceinline__ void hsplit(float v, __half& h, __half& l) {
    h = __float2half_rn(v);
    l = __float2half_rn(v - __half2float(h));
}
__device__ __forceinline__ uint32_t hpack2(float v0, float v1) {
    __half h0 = __float2half_rn(v0), h1 = __float2half_rn(v1);
    return (uint32_t)__half_as_ushort(h0) | ((uint32_t)__half_as_ushort(h1) << 16);
}
__device__ __forceinline__ uint32_t ffold(float x) {
    uint32_t b = __float_as_uint(x);
    return (b & 0x80000000u) ? ~b : (b | 0x80000000u);
}

// ============ core2: 2-plane A, single B, K-chunk 32, SW64, 3-stage (256 thr) ============
#define STG2 24576
#define GSMEM2 (3*24576)

__device__ __forceinline__ void load_chunk2(uint32_t base,
    const __half* __restrict__ Ah, const __half* __restrict__ Al,
    const __half* __restrict__ Bh,
    int arow0, int brow0, int Kdim, int kc)
{
    int t = threadIdx.x;
#pragma unroll
    for (int it = 0; it < 6; it++) {
        int idx = t + it * 256;
        int arr = idx >> 9;
        int r   = (idx >> 2) & 127;
        int c   = idx & 3;
        uint32_t so = swz64((uint32_t)(r * 64 + c * 16));
        const __half* src = (arr == 0) ? Ah : (arr == 1) ? Al : Bh;
        int row0 = (arr < 2) ? arow0 : brow0;
        cp16(base + arr * 8192 + so, src + (size_t)(row0 + r) * Kdim + kc * 32 + c * 8);
    }
    asm volatile("cp.async.commit_group;" ::: "memory");
}

__device__ __forceinline__ void gemm_core2(float acc[2][8][4],
    const __half* __restrict__ Ah, const __half* __restrict__ Al,
    const __half* __restrict__ Bh,
    int arow0, int brow0, int Kdim, int nchunk)
{
    extern __shared__ char smem[];
    uint32_t sb = smem_u32(smem);
    int t = threadIdx.x, lane = t & 31;
    int wm = (t >> 5) & 3, wn = t >> 7;

    uint32_t a_row = (uint32_t)(lane & 15);
    uint32_t a_kb  = (uint32_t)((lane >> 4) * 16);
    uint32_t b_row = (uint32_t)((lane & 7) + ((lane & 16) ? 8 : 0));
    uint32_t b_kb  = (uint32_t)(((lane >> 3) & 1) * 16);

    load_chunk2(sb,          Ah, Al, Bh, arow0, brow0, Kdim, 0);
    if (nchunk > 1) load_chunk2(sb + STG2,   Ah, Al, Bh, arow0, brow0, Kdim, 1);
    if (nchunk > 2) load_chunk2(sb + 2*STG2, Ah, Al, Bh, arow0, brow0, Kdim, 2);

    for (int kc = 0; kc < nchunk; kc++) {
        int rem = nchunk - kc - 1;
        if (rem >= 2)      { asm volatile("cp.async.wait_group 2;" ::: "memory"); }
        else if (rem == 1) { asm volatile("cp.async.wait_group 1;" ::: "memory"); }
        else               { asm volatile("cp.async.wait_group 0;" ::: "memory"); }
        __syncthreads();
        uint32_t base = sb + (kc % 3) * STG2;
#pragma unroll
        for (int ks = 0; ks < 2; ks++) {
            uint32_t aH[2][4], aL[2][4], bh[4][4];
#pragma unroll
            for (int mi = 0; mi < 2; mi++) {
                uint32_t off = swz64((uint32_t)((wm*32 + mi*16 + a_row)*64 + ks*32 + a_kb));
                ldsm4(aH[mi], base + off);
                ldsm4(aL[mi], base + 8192 + off);
            }
#pragma unroll
            for (int np = 0; np < 4; np++) {
                uint32_t off = swz64((uint32_t)((wn*64 + np*16 + b_row)*64 + ks*32 + b_kb));
                ldsm4(bh[np], base + 16384 + off);
            }
#pragma unroll
            for (int mi = 0; mi < 2; mi++)
#pragma unroll
                for (int np = 0; np < 4; np++) {
                    mma16816(acc[mi][np*2],   aH[mi], bh[np]);
                    mma16816(acc[mi][np*2+1], aH[mi], bh[np] + 2);
                }
#pragma unroll
            for (int mi = 0; mi < 2; mi++)
#pragma unroll
                for (int np = 0; np < 4; np++) {
                    mma16816(acc[mi][np*2],   aL[mi], bh[np]);
                    mma16816(acc[mi][np*2+1], aL[mi], bh[np] + 2);
                }
        }
        __syncthreads();
        if (kc + 3 < nchunk)
            load_chunk2(base, Ah, Al, Bh, arow0, brow0, Kdim, kc + 3);
    }
}

// ============ core1w: 128 threads, 4 warps 2x2, warp tile 64x64, K-chunk 64 ============
#define STG1 32768
#define GSMEM1 (3*32768)

__device__ __forceinline__ void load_chunk1w(uint32_t base,
    const __half* __restrict__ A, const __half* __restrict__ B,
    int arow0, int brow0, int Kdim, int kc)
{
    int t = threadIdx.x;
#pragma unroll
    for (int it = 0; it < 16; it++) {
        int idx = t + it * 128;
        int arr = idx >> 10;
        int r   = (idx >> 3) & 127;
        int c   = idx & 7;
        uint32_t so = swz128((uint32_t)(r * 128 + c * 16));
        const __half* src = arr ? B : A;
        int row0 = arr ? brow0 : arow0;
        cp16(base + arr * 16384 + so, src + (size_t)(row0 + r) * Kdim + kc * 64 + c * 8);
    }
    asm volatile("cp.async.commit_group;" ::: "memory");
}

__device__ __forceinline__ void gemm_core1w(float acc[4][8][4],
    const __half* __restrict__ A, const __half* __restrict__ B,
    int arow0, int brow0, int Kdim, int nchunk)
{
    extern __shared__ char smem[];
    uint32_t sb = smem_u32(smem);
    int t = threadIdx.x, lane = t & 31;
    int wm = (t >> 5) & 1, wn = t >> 6;
    uint32_t a_row = (uint32_t)(lane & 15);
    uint32_t a_kb  = (uint32_t)((lane >> 4) * 16);
    uint32_t b_row = (uint32_t)((lane & 7) + ((lane & 16) ? 8 : 0));
    uint32_t b_kb  = (uint32_t)(((lane >> 3) & 1) * 16);

    load_chunk1w(sb,          A, B, arow0, brow0, Kdim, 0);
    if (nchunk > 1) load_chunk1w(sb + STG1,   A, B, arow0, brow0, Kdim, 1);
    if (nchunk > 2) load_chunk1w(sb + 2*STG1, A, B, arow0, brow0, Kdim, 2);

    for (int kc = 0; kc < nchunk; kc++) {
        int rem = nchunk - kc - 1;
        if (rem >= 2)      { asm volatile("cp.async.wait_group 2;" ::: "memory"); }
        else if (rem == 1) { asm volatile("cp.async.wait_group 1;" ::: "memory"); }
        else               { asm volatile("cp.async.wait_group 0;" ::: "memory"); }
        __syncthreads();
        uint32_t base = sb + (kc % 3) * STG1;
#pragma unroll
        for (int ks = 0; ks < 4; ks++) {
            uint32_t aH[4][4], bh[4][4];
#pragma unroll
            for (int mi = 0; mi < 4; mi++)
                ldsm4(aH[mi], base + swz128((uint32_t)((wm*64 + mi*16 + a_row)*128 + ks*32 + a_kb)));
#pragma unroll
            for (int np = 0; np < 4; np++)
                ldsm4(bh[np], base + 16384 + swz128((uint32_t)((wn*64 + np*16 + b_row)*128 + ks*32 + b_kb)));
#pragma unroll
            for (int mi = 0; mi < 4; mi++)
#pragma unroll
                for (int np = 0; np < 4; np++) {
                    mma16816(acc[mi][np*2],   aH[mi], bh[np]);
                    mma16816(acc[mi][np*2+1], aH[mi], bh[np] + 2);
                }
        }
        __syncthreads();
        if (kc + 3 < nchunk)
            load_chunk1w(base, A, B, arow0, brow0, Kdim, kc + 3);
    }
}

// ===================== prep =====================
__global__ void prep_kernel(const float* __restrict__ w2, const float* __restrict__ w3,
                            const float* __restrict__ w4)
{
    int i = blockIdx.x * 256 + threadIdx.x;
    int stride = gridDim.x * 256;
    for (int j = i; j < 256*128; j += stride) W2q[j] = __float2half_rn(w2[j]);
    for (int j = i; j < 512*512; j += stride) {
        int n = j >> 9, k = j & 511;
        __half q = __float2half_rn(w3[j]);
        if (k < 256) W3gq[n*256 + k] = q;
        else         W3fq[n*256 + k - 256] = q;
    }
    for (int j = i; j < 384*512; j += stride) W4q[j] = __float2half_rn(w4[j]);
}

// ===================== FPS (unchanged, R12-validated) =====================
__global__ __launch_bounds__(1024) void fps_kernel(
    const float* __restrict__ pts, float* __restrict__ centers)
{
    extern __shared__ float sp[];
    int b = blockIdx.x;
    int t = threadIdx.x;
    int lane = t & 31, wid = t >> 5;
    const float* P = pts + (size_t)b * NP * 3;

    for (int idx = t; idx < NP * 3; idx += 1024) sp[idx] = P[idx];
    __syncthreads();

    float px[8], py[8], pz[8], md[8];
#pragma unroll
    for (int j = 0; j < 8; j++) {
        int n = j * 1024 + t;
        px[j] = sp[n*3+0]; py[j] = sp[n*3+1]; pz[j] = sp[n*3+2];
        md[j] = 1e10f;
    }

    __shared__ uint32_t s_v[2][32];
    __shared__ uint32_t s_i[2][32];

    int last = 0;
    for (int s = 0; s < NG; s++) {
        float cx = sp[last*3+0], cy = sp[last*3+1], cz = sp[last*3+2];
        if (t == 0) {
            float* C = centers + ((size_t)b * NG + s) * 3;
            C[0] = cx; C[1] = cy; C[2] = cz;
        }

        float bv; int bi;
        {
            float dx = px[0] - cx, dy = py[0] - cy, dz = pz[0] - cz;
            md[0] = fminf(md[0], fmaf(dz, dz, fmaf(dy, dy, __fmul_rn(dx, dx))));
            bv = md[0]; bi = t;
        }
#pragma unroll
        for (int j = 1; j < 8; j++) {
            float dx = px[j] - cx, dy = py[j] - cy, dz = pz[j] - cz;
            float d2 = fmaf(dz, dz, fmaf(dy, dy, __fmul_rn(dx, dx)));
            md[j] = fminf(md[j], d2);
            if (md[j] > bv) { bv = md[j]; bi = j * 1024 + t; }
        }
        uint32_t bits = __float_as_uint(bv);
        uint32_t vmax = __reduce_max_sync(0xffffffffu, bits);
        uint32_t cand = (bits == vmax) ? (uint32_t)bi : 0xffffffffu;
        uint32_t imin = __reduce_min_sync(0xffffffffu, cand);
        if (lane == 0) { s_v[s & 1][wid] = vmax; s_i[s & 1][wid] = imin; }
        __syncthreads();
        uint32_t v2 = s_v[s & 1][lane];
        uint32_t i2 = s_i[s & 1][lane];
        uint32_t vm2 = __reduce_max_sync(0xffffffffu, v2);
        uint32_t c2  = (v2 == vm2) ? i2 : 0xffffffffu;
        last = (int)__reduce_min_sync(0xffffffffu, c2);
    }
}

// ===================== grouping + stage1 (register-resident top-K) =====================
__global__ __launch_bounds__(256) void group_kernel(
    const float* __restrict__ pts, const float* __restrict__ centers,
    const float* __restrict__ w1,
    const float* __restrict__ bn1g, const float* __restrict__ bn1b,
    const float* __restrict__ bn1m, const float* __restrict__ bn1v)
{
    __shared__ uint32_t rv[2][8];
    __shared__ uint32_t ri[2][8];
    __shared__ int      sel[NK];
    __shared__ float    PTS[NK*3];

    int m = blockIdx.x;
    int b = m >> 9;
    int t = threadIdx.x;
    int lane = t & 31, wid = t >> 5;
    const float* P = pts + (size_t)b * NP * 3;

    float cx = centers[m*3+0], cy = centers[m*3+1], cz = centers[m*3+2];
    float cn = fmaf(cz, cz, fmaf(cy, cy, __fmul_rn(cx, cx)));

    // thread t owns contiguous points [t*32, t*32+32)
    int base = t * 32;
    uint32_t du[32];
    uint32_t bu = 0xffffffffu; int bi = base;
#pragma unroll
    for (int j = 0; j < 32; j++) {
        int n = base + j;
        float x = P[n*3+0], y = P[n*3+1], z = P[n*3+2];
        float pn  = fmaf(z, z, fmaf(y, y, __fmul_rn(x, x)));
        float dot = fmaf(cz, z, fmaf(cy, y, __fmul_rn(cx, x)));
        du[j] = ffold(__fadd_rn(cn, pn) - 2.0f * dot);
        if (du[j] < bu) { bu = du[j]; bi = n; }
    }

    for (int p = 0; p < NK; p++) {
        uint32_t vmin = __reduce_min_sync(0xffffffffu, bu);
        uint32_t cand = (bu == vmin) ? (uint32_t)bi : 0xffffffffu;
        uint32_t imin = __reduce_min_sync(0xffffffffu, cand);
        if (lane == 0) { rv[p & 1][wid] = vmin; ri[p & 1][wid] = imin; }
        __syncthreads();
        uint32_t v2 = (lane < 8) ? rv[p & 1][lane] : 0xffffffffu;
        uint32_t vm2 = __reduce_min_sync(0xffffffffu, v2);
        uint32_t c2  = (lane < 8 && v2 == vm2) ? ri[p & 1][lane] : 0xffffffffu;
        uint32_t fi  = __reduce_min_sync(0xffffffffu, c2);
        if (t == (int)(fi >> 5)) {
            sel[p] = (int)fi;
            // clear chosen (constant-indexed) and rescan local 32
#pragma unroll
            for (int j = 0; j < 32; j++)
                if (base + j == (int)fi) du[j] = 0xffffffffu;
            bu = 0xffffffffu; bi = base;
#pragma unroll
            for (int j = 0; j < 32; j++)
                if (du[j] < bu) { bu = du[j]; bi = base + j; }
        }
    }
    __syncthreads();

    if (t < NK * 3) {
        int k = t / 3, c = t % 3;
        int n = sel[k];
        float cv = (c == 0) ? cx : (c == 1) ? cy : cz;
        PTS[t] = P[n*3+c] - cv;
    }
    __syncthreads();

    {
        int c  = t >> 1;
        int k0 = (t & 1) * 16;
        float wx = w1[c*3+0], wy = w1[c*3+1], wz = w1[c*3+2];
        float sc = bn1g[c] * rsqrtf(bn1v[c] + 1e-5f);
        float sh = fmaf(-bn1m[c], sc, bn1b[c]);
#pragma unroll
        for (int kk = 0; kk < 16; kk++) {
            int k = k0 + kk;
            float v = fmaf(PTS[k*3+2], wz, fmaf(PTS[k*3+1], wy, PTS[k*3+0] * wx));
            v = fmaxf(fmaf(v, sc, sh), 0.f);
            __half h, l; hsplit(v, h, l);
            size_t o = ((size_t)m * NK + k) * 128 + c;
            F1h[o] = h;
            F1l[o] = l;
        }
    }
}

// ===================== gemm2 (unchanged): F2 = F1 @ W2^T + b2 ; GM = group max =====================
__global__ __launch_bounds__(256, 2) void gemm2_kernel(const float* __restrict__ b2)
{
    int mtile = blockIdx.x >> 1, nt = blockIdx.x & 1;
    float acc[2][8][4] = {};
    gemm_core2(acc, F1h, F1l, W2q, mtile*128, nt*128, 128, 4);

    int t = threadIdx.x, lane = t & 31;
    int wm = (t >> 5) & 3, wn = t >> 7;
    int rb = wm*32 + (lane >> 2);
    int g  = mtile*4 + wm;
#pragma unroll
    for (int ni = 0; ni < 8; ni++) {
        int c = nt*128 + wn*64 + ni*8 + (lane & 3)*2;
        float bb0 = b2[c], bb1 = b2[c+1];
        float g0 = NEG_INF, g1 = NEG_INF;
#pragma unroll
        for (int mi = 0; mi < 2; mi++) {
            size_t row = (size_t)mtile*128 + rb + mi*16;
            float v0 = acc[mi][ni][0] + bb0, v1 = acc[mi][ni][1] + bb1;
            float v2 = acc[mi][ni][2] + bb0, v3 = acc[mi][ni][3] + bb1;
            *(uint32_t*)(F2q + row*256 + c)     = hpack2(v0, v1);
            *(uint32_t*)(F2q + (row+8)*256 + c) = hpack2(v2, v3);
            g0 = fmaxf(g0, fmaxf(v0, v2));
            g1 = fmaxf(g1, fmaxf(v1, v3));
        }
#pragma unroll
        for (int off = 4; off <= 16; off <<= 1) {
            g0 = fmaxf(g0, __shfl_xor_sync(0xffffffffu, g0, off));
            g1 = fmaxf(g1, __shfl_xor_sync(0xffffffffu, g1, off));
        }
        if (lane < 4)
            *(uint32_t*)(GMq + (size_t)g*256 + c) = hpack2(g0, g1);
    }
}

// ===================== gemm3g (core1w): G3 = GM @ W3g^T =====================
__global__ __launch_bounds__(128, 2) void gemm3g_kernel()
{
    int mtile = blockIdx.x >> 2, nt = blockIdx.x & 3;
    float acc[4][8][4] = {};
    gemm_core1w(acc, GMq, W3gq, mtile*128, nt*128, 256, 4);

    int t = threadIdx.x, lane = t & 31;
    int wm = (t >> 5) & 1, wn = t >> 6;
#pragma unroll
    for (int ni = 0; ni < 8; ni++) {
        int c = nt*128 + wn*64 + ni*8 + (lane & 3)*2;
#pragma unroll
        for (int mi = 0; mi < 4; mi++) {
            size_t row = (size_t)mtile*128 + wm*64 + mi*16 + (lane >> 2);
            *(float2*)(G3 + row*512 + c)     = make_float2(acc[mi][ni][0], acc[mi][ni][1]);
            *(float2*)(G3 + (row+8)*512 + c) = make_float2(acc[mi][ni][2], acc[mi][ni][3]);
        }
    }
}

// ===================== gemm3f (core1w): F3 = relu(bn2(F2 @ W3f^T + G3)) =====================
__global__ __launch_bounds__(128, 2) void gemm3f_kernel(
    const float* __restrict__ bn2g, const float* __restrict__ bn2b,
    const float* __restrict__ bn2m, const float* __restrict__ bn2v)
{
    int mtile = blockIdx.x >> 2, nt = blockIdx.x & 3;
    float acc[4][8][4] = {};
    gemm_core1w(acc, F2q, W3fq, mtile*128, nt*128, 256, 4);

    extern __shared__ char smem[];
    float* sSC = (float*)smem;        // [128]
    float* sSH = sSC + 128;           // [128]
    float* sG  = sSH + 128;           // [4][128]
    int t = threadIdx.x;
    {
        int nl = nt*128 + t;
        float sc = bn2g[nl] * rsqrtf(bn2v[nl] + 1e-5f);
        sSC[t] = sc;
        sSH[t] = fmaf(-bn2m[nl], sc, bn2b[nl]);
    }
#pragma unroll
    for (int e = t; e < 512; e += 128)
        sG[e] = G3[(size_t)(mtile*4 + (e >> 7))*512 + nt*128 + (e & 127)];
    __syncthreads();

    int lane = t & 31;
    int wm = (t >> 5) & 1, wn = t >> 6;
#pragma unroll
    for (int ni = 0; ni < 8; ni++) {
        int lc = wn*64 + ni*8 + (lane & 3)*2;
        int c  = nt*128 + lc;
        float sc0 = sSC[lc], sc1 = sSC[lc+1];
        float sh0 = sSH[lc], sh1 = sSH[lc+1];
#pragma unroll
        for (int mi = 0; mi < 4; mi++) {
            int rloc = wm*64 + mi*16 + (lane >> 2);   // local row in [0,128)
            int gi = rloc >> 5;                        // group index within tile
            float gv0 = sG[gi*128 + lc], gv1 = sG[gi*128 + lc + 1];
            int gi8 = (rloc + 8) >> 5;
            float gw0 = sG[gi8*128 + lc], gw1 = sG[gi8*128 + lc + 1];
            size_t row = (size_t)mtile*128 + rloc;
            float v0 = fmaxf(fmaf(acc[mi][ni][0] + gv0, sc0, sh0), 0.f);
            float v1 = fmaxf(fmaf(acc[mi][ni][1] + gv1, sc1, sh1), 0.f);
            float v2 = fmaxf(fmaf(acc[mi][ni][2] + gw0, sc0, sh0), 0.f);
            float v3 = fmaxf(fmaf(acc[mi][ni][3] + gw1, sc1, sh1), 0.f);
            *(uint32_t*)(F3q + row*512 + c)     = hpack2(v0, v1);
            *(uint32_t*)(F3q + (row+8)*512 + c) = hpack2(v2, v3);
        }
    }
}

// ===================== gemm4 (core1w): tokens = group max of (F3 @ W4^T + b4) =====================
__global__ __launch_bounds__(128, 2) void gemm4_kernel(const float* __restrict__ b4,
                                                       float* __restrict__ tokens)
{
    int mtile = blockIdx.x / 3, nt = blockIdx.x % 3;
    float acc[4][8][4] = {};
    gemm_core1w(acc, F3q, W4q, mtile*128, nt*128, 512, 8);

    int t = threadIdx.x, lane = t & 31;
    int wm = (t >> 5) & 1, wn = t >> 6;
    int g0base = mtile*4 + wm*2;   // warp covers rows wm*64..wm*64+63 = groups g0base, g0base+1
#pragma unroll
    for (int ni = 0; ni < 8; ni++) {
        int c = nt*128 + wn*64 + ni*8 + (lane & 3)*2;
        float bb0 = b4[c], bb1 = b4[c+1];
        // group A: mi 0,1 (rows 0-31 of warp slice); group B: mi 2,3
        float a0 = NEG_INF, a1 = NEG_INF, c0 = NEG_INF, c1 = NEG_INF;
#pragma unroll
        for (int mi = 0; mi < 2; mi++) {
            a0 = fmaxf(a0, fmaxf(acc[mi][ni][0], acc[mi][ni][2]));
            a1 = fmaxf(a1, fmaxf(acc[mi][ni][1], acc[mi][ni][3]));
            c0 = fmaxf(c0, fmaxf(acc[mi+2][ni][0], acc[mi+2][ni][2]));
            c1 = fmaxf(c1, fmaxf(acc[mi+2][ni][1], acc[mi+2][ni][3]));
        }
        a0 += bb0; a1 += bb1; c0 += bb0; c1 += bb1;
#pragma unroll
        for (int off = 4; off <= 16; off <<= 1) {
            a0 = fmaxf(a0, __shfl_xor_sync(0xffffffffu, a0, off));
            a1 = fmaxf(a1, __shfl_xor_sync(0xffffffffu, a1, off));
            c0 = fmaxf(c0, __shfl_xor_sync(0xffffffffu, c0, off));
            c1 = fmaxf(c1, __shfl_xor_sync(0xffffffffu, c1, off));
        }
        if (lane < 4) {
            *(float2*)(tokens + (size_t)g0base*TOK + c)     = make_float2(a0, a1);
            *(float2*)(tokens + (size_t)(g0base+1)*TOK + c) = make_float2(c0, c1);
        }
    }
}

// =====================================================================
extern "C" void kernel_launch(void* const* d_in, const int* in_sizes, int n_in,
                              void* d_out, int out_size)
{
    const float* points = (const float*)d_in[0];
    const float* w1     = (const float*)d_in[1];
    const float* bn1g   = (const float*)d_in[2];
    const float* bn1b   = (const float*)d_in[3];
    const float* bn1m   = (const float*)d_in[4];
    const float* bn1v   = (const float*)d_in[5];
    const float* w2     = (const float*)d_in[6];
    const float* b2     = (const float*)d_in[7];
    const float* w3     = (const float*)d_in[8];
    const float* bn2g   = (const float*)d_in[9];
    const float* bn2b   = (const float*)d_in[10];
    const float* bn2m   = (const float*)d_in[11];
    const float* bn2v   = (const float*)d_in[12];
    const float* w4     = (const float*)d_in[13];
    const float* b4     = (const float*)d_in[14];

    float* tokens  = (float*)d_out;
    float* centers = (float*)d_out + (size_t)NM * TOK;

    static bool attr_done = false;
    if (!attr_done) {
        cudaFuncSetAttribute(fps_kernel,    cudaFuncAttributeMaxDynamicSharedMemorySize, NP*3*4);
        cudaFuncSetAttribute(gemm2_kernel,  cudaFuncAttributeMaxDynamicSharedMemorySize, GSMEM2);
        cudaFuncSetAttribute(gemm3g_kernel, cudaFuncAttributeMaxDynamicSharedMemorySize, GSMEM1);
        cudaFuncSetAttribute(gemm3f_kernel, cudaFuncAttributeMaxDynamicSharedMemorySize, GSMEM1);
        cudaFuncSetAttribute(gemm4_kernel,  cudaFuncAttributeMaxDynamicSharedMemorySize, GSMEM1);
        attr_done = true;
    }

    prep_kernel<<<256, 256>>>(w2, w3, w4);
    fps_kernel<<<NB, 1024, NP*3*4>>>(points, centers);
    group_kernel<<<NM, 256>>>(points, centers, w1, bn1g, bn1b, bn1m, bn1v);
    gemm2_kernel <<<4096, 256, GSMEM2>>>(b2);
    gemm3g_kernel<<<256,  128, GSMEM1>>>();
    gemm3f_kernel<<<8192, 128, GSMEM1>>>(bn2g, bn2b, bn2m, bn2v);
    gemm4_kernel <<<6144, 128, GSMEM1>>>(b4, tokens);
}

// round 15
// speedup vs baseline: 1.0418x; 1.0418x over previous
#include <cuda_runtime.h>
#include <cuda_fp16.h>
#include <cstdint>

#define NB 16
#define NP 8192
#define NG 512
#define NK 32
#define TOK 384
#define NM (NB*NG)          // 8192 groups
#define MTOT (NM*NK)        // 262144 rows

#define NEG_INF __int_as_float(0xff800000)

typedef unsigned long long ull;

// ===================== global scratch =====================
__device__ __align__(16) __half F1h[(size_t)MTOT*128];
__device__ __align__(16) __half F1l[(size_t)MTOT*128];
__device__ __align__(16) __half F2q[(size_t)MTOT*256];
__device__ __align__(16) __half F3q[(size_t)MTOT*512];
__device__ __align__(16) __half GMq[(size_t)NM*256];
__device__ __align__(16) float  G3[(size_t)NM*512];
__device__ __align__(16) __half W2q[256*128];
__device__ __align__(16) __half W3gq[512*256];
__device__ __align__(16) __half W3fq[512*256];
__device__ __align__(16) __half W4q[384*512];

// ===================== helpers =====================
__device__ __forceinline__ uint32_t smem_u32(const void* p) {
    uint32_t a;
    asm("{ .reg .u64 t; cvta.to.shared.u64 t, %1; cvt.u32.u64 %0, t; }" : "=r"(a) : "l"(p));
    return a;
}
__device__ __forceinline__ uint32_t swz64(uint32_t o)  { return o ^ ((o >> 3) & 0x30); }
__device__ __forceinline__ uint32_t swz128(uint32_t o) { return o ^ ((o >> 3) & 0x70); }

__device__ __forceinline__ void cp16(uint32_t d, const void* s) {
    asm volatile("cp.async.cg.shared.global [%0], [%1], 16;" :: "r"(d), "l"(s));
}
__device__ __forceinline__ void ldsm4(uint32_t* r, uint32_t addr) {
    asm volatile("ldmatrix.sync.aligned.m8n8.x4.shared.b16 {%0,%1,%2,%3}, [%4];"
        : "=r"(r[0]), "=r"(r[1]), "=r"(r[2]), "=r"(r[3]) : "r"(addr));
}
__device__ __forceinline__ void mma16816(float* d, const uint32_t* a, const uint32_t* b) {
    asm volatile("mma.sync.aligned.m16n8k16.row.col.f32.f16.f16.f32 "
        "{%0,%1,%2,%3}, {%4,%5,%6,%7}, {%8,%9}, {%0,%1,%2,%3};"
        : "+f"(d[0]), "+f"(d[1]), "+f"(d[2]), "+f"(d[3])
        : "r"(a[0]), "r"(a[1]), "r"(a[2]), "r"(a[3]), "r"(b[0]), "r"(b[1]));
}
__device__ __forceinline__ void hsplit(float v, __half& h, __half& l) {
    h = __float2half_rn(v);
    l = __float2half_rn(v - __half2float(h));
}
__device__ __forceinline__ uint32_t hpack2(float v0, float v1) {
    __half h0 = __float2half_rn(v0), h1 = __float2half_rn(v1);
    return (uint32_t)__half_as_ushort(h0) | ((uint32_t)__half_as_ushort(h1) << 16);
}
__device__ __forceinline__ uint32_t ffold(float x) {
    uint32_t b = __float_as_uint(x);
    return (b & 0x80000000u) ? ~b : (b | 0x80000000u);
}

// ============ core2: 2-plane A, single B, K-chunk 32, SW64, 3-stage ============
#define STG2 24576
#define GSMEM2 (3*24576)

__device__ __forceinline__ void load_chunk2(uint32_t base,
    const __half* __restrict__ Ah, const __half* __restrict__ Al,
    const __half* __restrict__ Bh,
    int arow0, int brow0, int Kdim, int kc)
{
    int t = threadIdx.x;
#pragma unroll
    for (int it = 0; it < 6; it++) {
        int idx = t + it * 256;
        int arr = idx >> 9;
        int r   = (idx >> 2) & 127;
        int c   = idx & 3;
        uint32_t so = swz64((uint32_t)(r * 64 + c * 16));
        const __half* src = (arr == 0) ? Ah : (arr == 1) ? Al : Bh;
        int row0 = (arr < 2) ? arow0 : brow0;
        cp16(base + arr * 8192 + so, src + (size_t)(row0 + r) * Kdim + kc * 32 + c * 8);
    }
    asm volatile("cp.async.commit_group;" ::: "memory");
}

__device__ __forceinline__ void gemm_core2(float acc[2][8][4],
    const __half* __restrict__ Ah, const __half* __restrict__ Al,
    const __half* __restrict__ Bh,
    int arow0, int brow0, int Kdim, int nchunk)
{
    extern __shared__ char smem[];
    uint32_t sb = smem_u32(smem);
    int t = threadIdx.x, lane = t & 31;
    int wm = (t >> 5) & 3, wn = t >> 7;

    uint32_t a_row = (uint32_t)(lane & 15);
    uint32_t a_kb  = (uint32_t)((lane >> 4) * 16);
    uint32_t b_row = (uint32_t)((lane & 7) + ((lane & 16) ? 8 : 0));
    uint32_t b_kb  = (uint32_t)(((lane >> 3) & 1) * 16);

    load_chunk2(sb,          Ah, Al, Bh, arow0, brow0, Kdim, 0);
    if (nchunk > 1) load_chunk2(sb + STG2,   Ah, Al, Bh, arow0, brow0, Kdim, 1);
    if (nchunk > 2) load_chunk2(sb + 2*STG2, Ah, Al, Bh, arow0, brow0, Kdim, 2);

    for (int kc = 0; kc < nchunk; kc++) {
        int rem = nchunk - kc - 1;
        if (rem >= 2)      { asm volatile("cp.async.wait_group 2;" ::: "memory"); }
        else if (rem == 1) { asm volatile("cp.async.wait_group 1;" ::: "memory"); }
        else               { asm volatile("cp.async.wait_group 0;" ::: "memory"); }
        __syncthreads();
        uint32_t base = sb + (kc % 3) * STG2;
#pragma unroll
        for (int ks = 0; ks < 2; ks++) {
            uint32_t aH[2][4], aL[2][4], bh[4][4];
#pragma unroll
            for (int mi = 0; mi < 2; mi++) {
                uint32_t off = swz64((uint32_t)((wm*32 + mi*16 + a_row)*64 + ks*32 + a_kb));
                ldsm4(aH[mi], base + off);
                ldsm4(aL[mi], base + 8192 + off);
            }
#pragma unroll
            for (int np = 0; np < 4; np++) {
                uint32_t off = swz64((uint32_t)((wn*64 + np*16 + b_row)*64 + ks*32 + b_kb));
                ldsm4(bh[np], base + 16384 + off);
            }
#pragma unroll
            for (int mi = 0; mi < 2; mi++)
#pragma unroll
                for (int np = 0; np < 4; np++) {
                    mma16816(acc[mi][np*2],   aH[mi], bh[np]);
                    mma16816(acc[mi][np*2+1], aH[mi], bh[np] + 2);
                }
#pragma unroll
            for (int mi = 0; mi < 2; mi++)
#pragma unroll
                for (int np = 0; np < 4; np++) {
                    mma16816(acc[mi][np*2],   aL[mi], bh[np]);
                    mma16816(acc[mi][np*2+1], aL[mi], bh[np] + 2);
                }
        }
        __syncthreads();
        if (kc + 3 < nchunk)
            load_chunk2(base, Ah, Al, Bh, arow0, brow0, Kdim, kc + 3);
    }
}

// ============ core1: single-plane A & B, K-chunk 64, SW128, 3-stage, 256 thr ============
#define STG1 32768
#define GSMEM1 (3*32768)

__device__ __forceinline__ void load_chunk1(uint32_t base,
    const __half* __restrict__ A, const __half* __restrict__ B,
    int arow0, int brow0, int Kdim, int kc)
{
    int t = threadIdx.x;
#pragma unroll
    for (int it = 0; it < 8; it++) {
        int idx = t + it * 256;
        int arr = idx >> 10;
        int r   = (idx >> 3) & 127;
        int c   = idx & 7;
        uint32_t so = swz128((uint32_t)(r * 128 + c * 16));
        const __half* src = arr ? B : A;
        int row0 = arr ? brow0 : arow0;
        cp16(base + arr * 16384 + so, src + (size_t)(row0 + r) * Kdim + kc * 64 + c * 8);
    }
    asm volatile("cp.async.commit_group;" ::: "memory");
}
__device__ __forceinline__ void gemm_core1(float acc[2][8][4],
    const __half* __restrict__ A, const __half* __restrict__ B,
    int arow0, int brow0, int Kdim, int nchunk)
{
    extern __shared__ char smem[];
    uint32_t sb = smem_u32(smem);
    int t = threadIdx.x, lane = t & 31;
    int wm = (t >> 5) & 3, wn = t >> 7;
    uint32_t a_row = (uint32_t)(lane & 15);
    uint32_t a_kb  = (uint32_t)((lane >> 4) * 16);
    uint32_t b_row = (uint32_t)((lane & 7) + ((lane & 16) ? 8 : 0));
    uint32_t b_kb  = (uint32_t)(((lane >> 3) & 1) * 16);

    load_chunk1(sb,          A, B, arow0, brow0, Kdim, 0);
    if (nchunk > 1) load_chunk1(sb + STG1,   A, B, arow0, brow0, Kdim, 1);
    if (nchunk > 2) load_chunk1(sb + 2*STG1, A, B, arow0, brow0, Kdim, 2);

    for (int kc = 0; kc < nchunk; kc++) {
        int rem = nchunk - kc - 1;
        if (rem >= 2)      { asm volatile("cp.async.wait_group 2;" ::: "memory"); }
        else if (rem == 1) { asm volatile("cp.async.wait_group 1;" ::: "memory"); }
        else               { asm volatile("cp.async.wait_group 0;" ::: "memory"); }
        __syncthreads();
        uint32_t base = sb + (kc % 3) * STG1;
#pragma unroll
        for (int ks = 0; ks < 4; ks++) {
            uint32_t aH[2][4], bh[4][4];
#pragma unroll
            for (int mi = 0; mi < 2; mi++)
                ldsm4(aH[mi], base + swz128((uint32_t)((wm*32 + mi*16 + a_row)*128 + ks*32 + a_kb)));
#pragma unroll
            for (int np = 0; np < 4; np++)
                ldsm4(bh[np], base + 16384 + swz128((uint32_t)((wn*64 + np*16 + b_row)*128 + ks*32 + b_kb)));
#pragma unroll
            for (int mi = 0; mi < 2; mi++)
#pragma unroll
                for (int np = 0; np < 4; np++) {
                    mma16816(acc[mi][np*2],   aH[mi], bh[np]);
                    mma16816(acc[mi][np*2+1], aH[mi], bh[np] + 2);
                }
        }
        __syncthreads();
        if (kc + 3 < nchunk)
            load_chunk1(base, A, B, arow0, brow0, Kdim, kc + 3);
    }
}

// ===================== prep =====================
__global__ void prep_kernel(const float* __restrict__ w2, const float* __restrict__ w3,
                            const float* __restrict__ w4)
{
    int i = blockIdx.x * 256 + threadIdx.x;
    int stride = gridDim.x * 256;
    for (int j = i; j < 256*128; j += stride) W2q[j] = __float2half_rn(w2[j]);
    for (int j = i; j < 512*512; j += stride) {
        int n = j >> 9, k = j & 511;
        __half q = __float2half_rn(w3[j]);
        if (k < 256) W3gq[n*256 + k] = q;
        else         W3fq[n*256 + k - 256] = q;
    }
    for (int j = i; j < 384*512; j += stride) W4q[j] = __float2half_rn(w4[j]);
}

// ===================== FPS (R12-validated) =====================
__global__ __launch_bounds__(1024) void fps_kernel(
    const float* __restrict__ pts, float* __restrict__ centers)
{
    extern __shared__ float sp[];
    int b = blockIdx.x;
    int t = threadIdx.x;
    int lane = t & 31, wid = t >> 5;
    const float* P = pts + (size_t)b * NP * 3;

    for (int idx = t; idx < NP * 3; idx += 1024) sp[idx] = P[idx];
    __syncthreads();

    float px[8], py[8], pz[8], md[8];
#pragma unroll
    for (int j = 0; j < 8; j++) {
        int n = j * 1024 + t;
        px[j] = sp[n*3+0]; py[j] = sp[n*3+1]; pz[j] = sp[n*3+2];
        md[j] = 1e10f;
    }

    __shared__ uint32_t s_v[2][32];
    __shared__ uint32_t s_i[2][32];

    int last = 0;
    for (int s = 0; s < NG; s++) {
        float cx = sp[last*3+0], cy = sp[last*3+1], cz = sp[last*3+2];
        if (t == 0) {
            float* C = centers + ((size_t)b * NG + s) * 3;
            C[0] = cx; C[1] = cy; C[2] = cz;
        }

        float bv; int bi;
        {
            float dx = px[0] - cx, dy = py[0] - cy, dz = pz[0] - cz;
            md[0] = fminf(md[0], fmaf(dz, dz, fmaf(dy, dy, __fmul_rn(dx, dx))));
            bv = md[0]; bi = t;
        }
#pragma unroll
        for (int j = 1; j < 8; j++) {
            float dx = px[j] - cx, dy = py[j] - cy, dz = pz[j] - cz;
            float d2 = fmaf(dz, dz, fmaf(dy, dy, __fmul_rn(dx, dx)));
            md[j] = fminf(md[j], d2);
            if (md[j] > bv) { bv = md[j]; bi = j * 1024 + t; }
        }
        uint32_t bits = __float_as_uint(bv);
        uint32_t vmax = __reduce_max_sync(0xffffffffu, bits);
        uint32_t cand = (bits == vmax) ? (uint32_t)bi : 0xffffffffu;
        uint32_t imin = __reduce_min_sync(0xffffffffu, cand);
        if (lane == 0) { s_v[s & 1][wid] = vmax; s_i[s & 1][wid] = imin; }
        __syncthreads();
        uint32_t v2 = s_v[s & 1][lane];
        uint32_t i2 = s_i[s & 1][lane];
        uint32_t vm2 = __reduce_max_sync(0xffffffffu, v2);
        uint32_t c2  = (v2 == vm2) ? i2 : 0xffffffffu;
        last = (int)__reduce_min_sync(0xffffffffu, c2);
    }
}

// ===================== grouping + stage1 (register-resident top-K; ONLY change vs 1330µs) =====================
__global__ __launch_bounds__(256) void group_kernel(
    const float* __restrict__ pts, const float* __restrict__ centers,
    const float* __restrict__ w1,
    const float* __restrict__ bn1g, const float* __restrict__ bn1b,
    const float* __restrict__ bn1m, const float* __restrict__ bn1v)
{
    __shared__ uint32_t rv[2][8];
    __shared__ uint32_t ri[2][8];
    __shared__ int      sel[NK];
    __shared__ float    PTS[NK*3];

    int m = blockIdx.x;
    int b = m >> 9;
    int t = threadIdx.x;
    int lane = t & 31, wid = t >> 5;
    const float* P = pts + (size_t)b * NP * 3;

    float cx = centers[m*3+0], cy = centers[m*3+1], cz = centers[m*3+2];
    float cn = fmaf(cz, cz, fmaf(cy, cy, __fmul_rn(cx, cx)));

    // thread t owns contiguous points [t*32, t*32+32)
    int base = t * 32;
    uint32_t du[32];
    uint32_t bu = 0xffffffffu; int bi = base;
#pragma unroll
    for (int j = 0; j < 32; j++) {
        int n = base + j;
        float x = P[n*3+0], y = P[n*3+1], z = P[n*3+2];
        float pn  = fmaf(z, z, fmaf(y, y, __fmul_rn(x, x)));
        float dot = fmaf(cz, z, fmaf(cy, y, __fmul_rn(cx, x)));
        du[j] = ffold(__fadd_rn(cn, pn) - 2.0f * dot);
        if (du[j] < bu) { bu = du[j]; bi = n; }
    }

    for (int p = 0; p < NK; p++) {
        uint32_t vmin = __reduce_min_sync(0xffffffffu, bu);
        uint32_t cand = (bu == vmin) ? (uint32_t)bi : 0xffffffffu;
        uint32_t imin = __reduce_min_sync(0xffffffffu, cand);
        if (lane == 0) { rv[p & 1][wid] = vmin; ri[p & 1][wid] = imin; }
        __syncthreads();
        uint32_t v2 = (lane < 8) ? rv[p & 1][lane] : 0xffffffffu;
        uint32_t vm2 = __reduce_min_sync(0xffffffffu, v2);
        uint32_t c2  = (lane < 8 && v2 == vm2) ? ri[p & 1][lane] : 0xffffffffu;
        uint32_t fi  = __reduce_min_sync(0xffffffffu, c2);
        if (t == (int)(fi >> 5)) {
            sel[p] = (int)fi;
#pragma unroll
            for (int j = 0; j < 32; j++)
                if (base + j == (int)fi) du[j] = 0xffffffffu;
            bu = 0xffffffffu; bi = base;
#pragma unroll
            for (int j = 0; j < 32; j++)
                if (du[j] < bu) { bu = du[j]; bi = base + j; }
        }
    }
    __syncthreads();

    if (t < NK * 3) {
        int k = t / 3, c = t % 3;
        int n = sel[k];
        float cv = (c == 0) ? cx : (c == 1) ? cy : cz;
        PTS[t] = P[n*3+c] - cv;
    }
    __syncthreads();

    {
        int c  = t >> 1;
        int k0 = (t & 1) * 16;
        float wx = w1[c*3+0], wy = w1[c*3+1], wz = w1[c*3+2];
        float sc = bn1g[c] * rsqrtf(bn1v[c] + 1e-5f);
        float sh = fmaf(-bn1m[c], sc, bn1b[c]);
#pragma unroll
        for (int kk = 0; kk < 16; kk++) {
            int k = k0 + kk;
            float v = fmaf(PTS[k*3+2], wz, fmaf(PTS[k*3+1], wy, PTS[k*3+0] * wx));
            v = fmaxf(fmaf(v, sc, sh), 0.f);
            __half h, l; hsplit(v, h, l);
            size_t o = ((size_t)m * NK + k) * 128 + c;
            F1h[o] = h;
            F1l[o] = l;
        }
    }
}

// ===================== GEMM kernels (exact 1330µs configuration) =====================

__global__ __launch_bounds__(256, 2) void gemm2_kernel(const float* __restrict__ b2)
{
    int mtile = blockIdx.x >> 1, nt = blockIdx.x & 1;
    float acc[2][8][4] = {};
    gemm_core2(acc, F1h, F1l, W2q, mtile*128, nt*128, 128, 4);

    int t = threadIdx.x, lane = t & 31;
    int wm = (t >> 5) & 3, wn = t >> 7;
    int rb = wm*32 + (lane >> 2);
    int g  = mtile*4 + wm;
#pragma unroll
    for (int ni = 0; ni < 8; ni++) {
        int c = nt*128 + wn*64 + ni*8 + (lane & 3)*2;
        float bb0 = b2[c], bb1 = b2[c+1];
        float g0 = NEG_INF, g1 = NEG_INF;
#pragma unroll
        for (int mi = 0; mi < 2; mi++) {
            size_t row = (size_t)mtile*128 + rb + mi*16;
            float v0 = acc[mi][ni][0] + bb0, v1 = acc[mi][ni][1] + bb1;
            float v2 = acc[mi][ni][2] + bb0, v3 = acc[mi][ni][3] + bb1;
            *(uint32_t*)(F2q + row*256 + c)     = hpack2(v0, v1);
            *(uint32_t*)(F2q + (row+8)*256 + c) = hpack2(v2, v3);
            g0 = fmaxf(g0, fmaxf(v0, v2));
            g1 = fmaxf(g1, fmaxf(v1, v3));
        }
#pragma unroll
        for (int off = 4; off <= 16; off <<= 1) {
            g0 = fmaxf(g0, __shfl_xor_sync(0xffffffffu, g0, off));
            g1 = fmaxf(g1, __shfl_xor_sync(0xffffffffu, g1, off));
        }
        if (lane < 4)
            *(uint32_t*)(GMq + (size_t)g*256 + c) = hpack2(g0, g1);
    }
}

__global__ __launch_bounds__(256, 2) void gemm3g_kernel()
{
    int mtile = blockIdx.x >> 2, nt = blockIdx.x & 3;
    float acc[2][8][4] = {};
    gemm_core1(acc, GMq, W3gq, mtile*128, nt*128, 256, 4);

    int t = threadIdx.x, lane = t & 31;
    int wm = (t >> 5) & 3, wn = t >> 7;
    int rb = wm*32 + (lane >> 2);
#pragma unroll
    for (int ni = 0; ni < 8; ni++) {
        int c = nt*128 + wn*64 + ni*8 + (lane & 3)*2;
#pragma unroll
        for (int mi = 0; mi < 2; mi++) {
            size_t row = (size_t)mtile*128 + rb + mi*16;
            *(float2*)(G3 + row*512 + c)     = make_float2(acc[mi][ni][0], acc[mi][ni][1]);
            *(float2*)(G3 + (row+8)*512 + c) = make_float2(acc[mi][ni][2], acc[mi][ni][3]);
        }
    }
}

__global__ __launch_bounds__(256, 2) void gemm3f_kernel(
    const float* __restrict__ bn2g, const float* __restrict__ bn2b,
    const float* __restrict__ bn2m, const float* __restrict__ bn2v)
{
    int mtile = blockIdx.x >> 2, nt = blockIdx.x & 3;
    float acc[2][8][4] = {};
    gemm_core1(acc, F2q, W3fq, mtile*128, nt*128, 256, 4);

    extern __shared__ char smem[];
    float* sSC = (float*)smem;
    float* sSH = sSC + 128;
    float* sG  = sSH + 128;
    int t = threadIdx.x;
    if (t < 128) {
        int nl = nt*128 + t;
        float sc = bn2g[nl] * rsqrtf(bn2v[nl] + 1e-5f);
        sSC[t] = sc;
        sSH[t] = fmaf(-bn2m[nl], sc, bn2b[nl]);
    }
#pragma unroll
    for (int e = t; e < 512; e += 256)
        sG[e] = G3[(size_t)(mtile*4 + (e >> 7))*512 + nt*128 + (e & 127)];
    __syncthreads();

    int lane = t & 31;
    int wm = (t >> 5) & 3, wn = t >> 7;
    int rb = wm*32 + (lane >> 2);
#pragma unroll
    for (int ni = 0; ni < 8; ni++) {
        int lc = wn*64 + ni*8 + (lane & 3)*2;
        int c  = nt*128 + lc;
        float sc0 = sSC[lc], sc1 = sSC[lc+1];
        float sh0 = sSH[lc], sh1 = sSH[lc+1];
        float gv0 = sG[wm*128 + lc], gv1 = sG[wm*128 + lc + 1];
#pragma unroll
        for (int mi = 0; mi < 2; mi++) {
            size_t row = (size_t)mtile*128 + rb + mi*16;
            float v0 = fmaxf(fmaf(acc[mi][ni][0] + gv0, sc0, sh0), 0.f);
            float v1 = fmaxf(fmaf(acc[mi][ni][1] + gv1, sc1, sh1), 0.f);
            float v2 = fmaxf(fmaf(acc[mi][ni][2] + gv0, sc0, sh0), 0.f);
            float v3 = fmaxf(fmaf(acc[mi][ni][3] + gv1, sc1, sh1), 0.f);
            *(uint32_t*)(F3q + row*512 + c)     = hpack2(v0, v1);
            *(uint32_t*)(F3q + (row+8)*512 + c) = hpack2(v2, v3);
        }
    }
}

__global__ __launch_bounds__(256, 2) void gemm4_kernel(const float* __restrict__ b4,
                                                       float* __restrict__ tokens)
{
    int mtile = blockIdx.x / 3, nt = blockIdx.x % 3;
    float acc[2][8][4] = {};
    gemm_core1(acc, F3q, W4q, mtile*128, nt*128, 512, 8);

    int t = threadIdx.x, lane = t & 31;
    int wm = (t >> 5) & 3, wn = t >> 7;
    int g = mtile*4 + wm;
#pragma unroll
    for (int ni = 0; ni < 8; ni++) {
        int c = nt*128 + wn*64 + ni*8 + (lane & 3)*2;
        float bb0 = b4[c], bb1 = b4[c+1];
        float g0 = NEG_INF, g1 = NEG_INF;
#pragma unroll
        for (int mi = 0; mi < 2; mi++) {
            g0 = fmaxf(g0, fmaxf(acc[mi][ni][0], acc[mi][ni][2]));
            g1 = fmaxf(g1, fmaxf(acc[mi][ni][1], acc[mi][ni][3]));
        }
        g0 += bb0; g1 += bb1;
#pragma unroll
        for (int off = 4; off <= 16; off <<= 1) {
            g0 = fmaxf(g0, __shfl_xor_sync(0xffffffffu, g0, off));
            g1 = fmaxf(g1, __shfl_xor_sync(0xffffffffu, g1, off));
        }
        if (lane < 4)
            *(float2*)(tokens + (size_t)g*TOK + c) = make_float2(g0, g1);
    }
}

// =====================================================================
extern "C" void kernel_launch(void* const* d_in, const int* in_sizes, int n_in,
                              void* d_out, int out_size)
{
    const float* points = (const float*)d_in[0];
    const float* w1     = (const float*)d_in[1];
    const float* bn1g   = (const float*)d_in[2];
    const float* bn1b   = (const float*)d_in[3];
    const float* bn1m   = (const float*)d_in[4];
    const float* bn1v   = (const float*)d_in[5];
    const float* w2     = (const float*)d_in[6];
    const float* b2     = (const float*)d_in[7];
    const float* w3     = (const float*)d_in[8];
    const float* bn2g   = (const float*)d_in[9];
    const float* bn2b   = (const float*)d_in[10];
    const float* bn2m   = (const float*)d_in[11];
    const float* bn2v   = (const float*)d_in[12];
    const float* w4     = (const float*)d_in[13];
    const float* b4     = (const float*)d_in[14];

    float* tokens  = (float*)d_out;
    float* centers = (float*)d_out + (size_t)NM * TOK;

    static bool attr_done = false;
    if (!attr_done) {
        cudaFuncSetAttribute(fps_kernel,    cudaFuncAttributeMaxDynamicSharedMemorySize, NP*3*4);
        cudaFuncSetAttribute(gemm2_kernel,  cudaFuncAttributeMaxDynamicSharedMemorySize, GSMEM2);
        cudaFuncSetAttribute(gemm3g_kernel, cudaFuncAttributeMaxDynamicSharedMemorySize, GSMEM1);
        cudaFuncSetAttribute(gemm3f_kernel, cudaFuncAttributeMaxDynamicSharedMemorySize, GSMEM1);
        cudaFuncSetAttribute(gemm4_kernel,  cudaFuncAttributeMaxDynamicSharedMemorySize, GSMEM1);
        attr_done = true;
    }

    prep_kernel<<<256, 256>>>(w2, w3, w4);
    fps_kernel<<<NB, 1024, NP*3*4>>>(points, centers);
    group_kernel<<<NM, 256>>>(points, centers, w1, bn1g, bn1b, bn1m, bn1v);
    gemm2_kernel <<<4096, 256, GSMEM2>>>(b2);
    gemm3g_kernel<<<256,  256, GSMEM1>>>();
    gemm3f_kernel<<<8192, 256, GSMEM1>>>(bn2g, bn2b, bn2m, bn2v);
    gemm4_kernel <<<6144, 256, GSMEM1>>>(b4, tokens);
}

// round 16
// speedup vs baseline: 1.5858x; 1.5222x over previous
#include <cuda_runtime.h>
#include <cuda_fp16.h>
#include <cstdint>

#define NB 16
#define NP 8192
#define NG 512
#define NK 32
#define TOK 384
#define NM (NB*NG)          // 8192 groups
#define MTOT (NM*NK)        // 262144 rows

#define NEG_INF __int_as_float(0xff800000)

typedef unsigned long long ull;

// ===================== global scratch =====================
__device__ __align__(16) __half F1h[(size_t)MTOT*128];
__device__ __align__(16) __half F1l[(size_t)MTOT*128];
__device__ __align__(16) __half F2q[(size_t)MTOT*256];
__device__ __align__(16) __half F3q[(size_t)MTOT*512];
__device__ __align__(16) __half GMq[(size_t)NM*256];
__device__ __align__(16) float  G3[(size_t)NM*512];
__device__ __align__(16) __half W2q[256*128];
__device__ __align__(16) __half W3gq[512*256];
__device__ __align__(16) __half W3fq[512*256];
__device__ __align__(16) __half W4q[384*512];

// ===================== helpers =====================
__device__ __forceinline__ uint32_t smem_u32(const void* p) {
    uint32_t a;
    asm("{ .reg .u64 t; cvta.to.shared.u64 t, %1; cvt.u32.u64 %0, t; }" : "=r"(a) : "l"(p));
    return a;
}
__device__ __forceinline__ uint32_t swz64(uint32_t o)  { return o ^ ((o >> 3) & 0x30); }
__device__ __forceinline__ uint32_t swz128(uint32_t o) { return o ^ ((o >> 3) & 0x70); }

__device__ __forceinline__ void cp16(uint32_t d, const void* s) {
    asm volatile("cp.async.cg.shared.global [%0], [%1], 16;" :: "r"(d), "l"(s));
}
__device__ __forceinline__ void ldsm4(uint32_t* r, uint32_t addr) {
    asm volatile("ldmatrix.sync.aligned.m8n8.x4.shared.b16 {%0,%1,%2,%3}, [%4];"
        : "=r"(r[0]), "=r"(r[1]), "=r"(r[2]), "=r"(r[3]) : "r"(addr));
}
__device__ __forceinline__ void mma16816(float* d, const uint32_t* a, const uint32_t* b) {
    asm volatile("mma.sync.aligned.m16n8k16.row.col.f32.f16.f16.f32 "
        "{%0,%1,%2,%3}, {%4,%5,%6,%7}, {%8,%9}, {%0,%1,%2,%3};"
        : "+f"(d[0]), "+f"(d[1]), "+f"(d[2]), "+f"(d[3])
        : "r"(a[0]), "r"(a[1]), "r"(a[2]), "r"(a[3]), "r"(b[0]), "r"(b[1]));
}
__device__ __forceinline__ void hsplit(float v, __half& h, __half& l) {
    h = __float2half_rn(v);
    l = __float2half_rn(v - __half2float(h));
}
__device__ __forceinline__ uint32_t hpack2(float v0, float v1) {
    __half h0 = __float2half_rn(v0), h1 = __float2half_rn(v1);
    return (uint32_t)__half_as_ushort(h0) | ((uint32_t)__half_as_ushort(h1) << 16);
}
__device__ __forceinline__ uint32_t ffold(float x) {
    uint32_t b = __float_as_uint(x);
    return (b & 0x80000000u) ? ~b : (b | 0x80000000u);
}

// ============ core2: 2-plane A, single B, K-chunk 32, SW64, 3-stage ============
#define STG2 24576
#define GSMEM2 (3*24576)

__device__ __forceinline__ void load_chunk2(uint32_t base,
    const __half* __restrict__ Ah, const __half* __restrict__ Al,
    const __half* __restrict__ Bh,
    int arow0, int brow0, int Kdim, int kc)
{
    int t = threadIdx.x;
#pragma unroll
    for (int it = 0; it < 6; it++) {
        int idx = t + it * 256;
        int arr = idx >> 9;
        int r   = (idx >> 2) & 127;
        int c   = idx & 3;
        uint32_t so = swz64((uint32_t)(r * 64 + c * 16));
        const __half* src = (arr == 0) ? Ah : (arr == 1) ? Al : Bh;
        int row0 = (arr < 2) ? arow0 : brow0;
        cp16(base + arr * 8192 + so, src + (size_t)(row0 + r) * Kdim + kc * 32 + c * 8);
    }
    asm volatile("cp.async.commit_group;" ::: "memory");
}

__device__ __forceinline__ void gemm_core2(float acc[2][8][4],
    const __half* __restrict__ Ah, const __half* __restrict__ Al,
    const __half* __restrict__ Bh,
    int arow0, int brow0, int Kdim, int nchunk)
{
    extern __shared__ char smem[];
    uint32_t sb = smem_u32(smem);
    int t = threadIdx.x, lane = t & 31;
    int wm = (t >> 5) & 3, wn = t >> 7;

    uint32_t a_row = (uint32_t)(lane & 15);
    uint32_t a_kb  = (uint32_t)((lane >> 4) * 16);
    uint32_t b_row = (uint32_t)((lane & 7) + ((lane & 16) ? 8 : 0));
    uint32_t b_kb  = (uint32_t)(((lane >> 3) & 1) * 16);

    load_chunk2(sb,          Ah, Al, Bh, arow0, brow0, Kdim, 0);
    if (nchunk > 1) load_chunk2(sb + STG2,   Ah, Al, Bh, arow0, brow0, Kdim, 1);
    if (nchunk > 2) load_chunk2(sb + 2*STG2, Ah, Al, Bh, arow0, brow0, Kdim, 2);

    for (int kc = 0; kc < nchunk; kc++) {
        int rem = nchunk - kc - 1;
        if (rem >= 2)      { asm volatile("cp.async.wait_group 2;" ::: "memory"); }
        else if (rem == 1) { asm volatile("cp.async.wait_group 1;" ::: "memory"); }
        else               { asm volatile("cp.async.wait_group 0;" ::: "memory"); }
        __syncthreads();
        uint32_t base = sb + (kc % 3) * STG2;
#pragma unroll
        for (int ks = 0; ks < 2; ks++) {
            uint32_t aH[2][4], aL[2][4], bh[4][4];
#pragma unroll
            for (int mi = 0; mi < 2; mi++) {
                uint32_t off = swz64((uint32_t)((wm*32 + mi*16 + a_row)*64 + ks*32 + a_kb));
                ldsm4(aH[mi], base + off);
                ldsm4(aL[mi], base + 8192 + off);
            }
#pragma unroll
            for (int np = 0; np < 4; np++) {
                uint32_t off = swz64((uint32_t)((wn*64 + np*16 + b_row)*64 + ks*32 + b_kb));
                ldsm4(bh[np], base + 16384 + off);
            }
#pragma unroll
            for (int mi = 0; mi < 2; mi++)
#pragma unroll
                for (int np = 0; np < 4; np++) {
                    mma16816(acc[mi][np*2],   aH[mi], bh[np]);
                    mma16816(acc[mi][np*2+1], aH[mi], bh[np] + 2);
                }
#pragma unroll
            for (int mi = 0; mi < 2; mi++)
#pragma unroll
                for (int np = 0; np < 4; np++) {
                    mma16816(acc[mi][np*2],   aL[mi], bh[np]);
                    mma16816(acc[mi][np*2+1], aL[mi], bh[np] + 2);
                }
        }
        __syncthreads();
        if (kc + 3 < nchunk)
            load_chunk2(base, Ah, Al, Bh, arow0, brow0, Kdim, kc + 3);
    }
}

// ============ core1: single-plane A & B, K-chunk 64, SW128, 3-stage, 256 thr ============
#define STG1 32768
#define GSMEM1 (3*32768)

__device__ __forceinline__ void load_chunk1(uint32_t base,
    const __half* __restrict__ A, const __half* __restrict__ B,
    int arow0, int brow0, int Kdim, int kc)
{
    int t = threadIdx.x;
#pragma unroll
    for (int it = 0; it < 8; it++) {
        int idx = t + it * 256;
        int arr = idx >> 10;
        int r   = (idx >> 3) & 127;
        int c   = idx & 7;
        uint32_t so = swz128((uint32_t)(r * 128 + c * 16));
        const __half* src = arr ? B : A;
        int row0 = arr ? brow0 : arow0;
        cp16(base + arr * 16384 + so, src + (size_t)(row0 + r) * Kdim + kc * 64 + c * 8);
    }
    asm volatile("cp.async.commit_group;" ::: "memory");
}
__device__ __forceinline__ void gemm_core1(float acc[2][8][4],
    const __half* __restrict__ A, const __half* __restrict__ B,
    int arow0, int brow0, int Kdim, int nchunk)
{
    extern __shared__ char smem[];
    uint32_t sb = smem_u32(smem);
    int t = threadIdx.x, lane = t & 31;
    int wm = (t >> 5) & 3, wn = t >> 7;
    uint32_t a_row = (uint32_t)(lane & 15);
    uint32_t a_kb  = (uint32_t)((lane >> 4) * 16);
    uint32_t b_row = (uint32_t)((lane & 7) + ((lane & 16) ? 8 : 0));
    uint32_t b_kb  = (uint32_t)(((lane >> 3) & 1) * 16);

    load_chunk1(sb,          A, B, arow0, brow0, Kdim, 0);
    if (nchunk > 1) load_chunk1(sb + STG1,   A, B, arow0, brow0, Kdim, 1);
    if (nchunk > 2) load_chunk1(sb + 2*STG1, A, B, arow0, brow0, Kdim, 2);

    for (int kc = 0; kc < nchunk; kc++) {
        int rem = nchunk - kc - 1;
        if (rem >= 2)      { asm volatile("cp.async.wait_group 2;" ::: "memory"); }
        else if (rem == 1) { asm volatile("cp.async.wait_group 1;" ::: "memory"); }
        else               { asm volatile("cp.async.wait_group 0;" ::: "memory"); }
        __syncthreads();
        uint32_t base = sb + (kc % 3) * STG1;
#pragma unroll
        for (int ks = 0; ks < 4; ks++) {
            uint32_t aH[2][4], bh[4][4];
#pragma unroll
            for (int mi = 0; mi < 2; mi++)
                ldsm4(aH[mi], base + swz128((uint32_t)((wm*32 + mi*16 + a_row)*128 + ks*32 + a_kb)));
#pragma unroll
            for (int np = 0; np < 4; np++)
                ldsm4(bh[np], base + 16384 + swz128((uint32_t)((wn*64 + np*16 + b_row)*128 + ks*32 + b_kb)));
#pragma unroll
            for (int mi = 0; mi < 2; mi++)
#pragma unroll
                for (int np = 0; np < 4; np++) {
                    mma16816(acc[mi][np*2],   aH[mi], bh[np]);
                    mma16816(acc[mi][np*2+1], aH[mi], bh[np] + 2);
                }
        }
        __syncthreads();
        if (kc + 3 < nchunk)
            load_chunk1(base, A, B, arow0, brow0, Kdim, kc + 3);
    }
}

// ===================== prep =====================
__global__ void prep_kernel(const float* __restrict__ w2, const float* __restrict__ w3,
                            const float* __restrict__ w4)
{
    int i = blockIdx.x * 256 + threadIdx.x;
    int stride = gridDim.x * 256;
    for (int j = i; j < 256*128; j += stride) W2q[j] = __float2half_rn(w2[j]);
    for (int j = i; j < 512*512; j += stride) {
        int n = j >> 9, k = j & 511;
        __half q = __float2half_rn(w3[j]);
        if (k < 256) W3gq[n*256 + k] = q;
        else         W3fq[n*256 + k - 256] = q;
    }
    for (int j = i; j < 384*512; j += stride) W4q[j] = __float2half_rn(w4[j]);
}

// ===================== FPS (R12-validated) =====================
__global__ __launch_bounds__(1024) void fps_kernel(
    const float* __restrict__ pts, float* __restrict__ centers)
{
    extern __shared__ float sp[];
    int b = blockIdx.x;
    int t = threadIdx.x;
    int lane = t & 31, wid = t >> 5;
    const float* P = pts + (size_t)b * NP * 3;

    for (int idx = t; idx < NP * 3; idx += 1024) sp[idx] = P[idx];
    __syncthreads();

    float px[8], py[8], pz[8], md[8];
#pragma unroll
    for (int j = 0; j < 8; j++) {
        int n = j * 1024 + t;
        px[j] = sp[n*3+0]; py[j] = sp[n*3+1]; pz[j] = sp[n*3+2];
        md[j] = 1e10f;
    }

    __shared__ uint32_t s_v[2][32];
    __shared__ uint32_t s_i[2][32];

    int last = 0;
    for (int s = 0; s < NG; s++) {
        float cx = sp[last*3+0], cy = sp[last*3+1], cz = sp[last*3+2];
        if (t == 0) {
            float* C = centers + ((size_t)b * NG + s) * 3;
            C[0] = cx; C[1] = cy; C[2] = cz;
        }

        float bv; int bi;
        {
            float dx = px[0] - cx, dy = py[0] - cy, dz = pz[0] - cz;
            md[0] = fminf(md[0], fmaf(dz, dz, fmaf(dy, dy, __fmul_rn(dx, dx))));
            bv = md[0]; bi = t;
        }
#pragma unroll
        for (int j = 1; j < 8; j++) {
            float dx = px[j] - cx, dy = py[j] - cy, dz = pz[j] - cz;
            float d2 = fmaf(dz, dz, fmaf(dy, dy, __fmul_rn(dx, dx)));
            md[j] = fminf(md[j], d2);
            if (md[j] > bv) { bv = md[j]; bi = j * 1024 + t; }
        }
        uint32_t bits = __float_as_uint(bv);
        uint32_t vmax = __reduce_max_sync(0xffffffffu, bits);
        uint32_t cand = (bits == vmax) ? (uint32_t)bi : 0xffffffffu;
        uint32_t imin = __reduce_min_sync(0xffffffffu, cand);
        if (lane == 0) { s_v[s & 1][wid] = vmax; s_i[s & 1][wid] = imin; }
        __syncthreads();
        uint32_t v2 = s_v[s & 1][lane];
        uint32_t i2 = s_i[s & 1][lane];
        uint32_t vm2 = __reduce_max_sync(0xffffffffu, v2);
        uint32_t c2  = (v2 == vm2) ? i2 : 0xffffffffu;
        last = (int)__reduce_min_sync(0xffffffffu, c2);
    }
}

// ===================== grouping + stage1 (register top-K, COALESCED ownership) =====================
__global__ __launch_bounds__(256) void group_kernel(
    const float* __restrict__ pts, const float* __restrict__ centers,
    const float* __restrict__ w1,
    const float* __restrict__ bn1g, const float* __restrict__ bn1b,
    const float* __restrict__ bn1m, const float* __restrict__ bn1v)
{
    __shared__ uint32_t rv[2][8];
    __shared__ uint32_t ri[2][8];
    __shared__ int      sel[NK];
    __shared__ float    PTS[NK*3];

    int m = blockIdx.x;
    int b = m >> 9;
    int t = threadIdx.x;
    int lane = t & 31, wid = t >> 5;
    const float* P = pts + (size_t)b * NP * 3;

    float cx = centers[m*3+0], cy = centers[m*3+1], cz = centers[m*3+2];
    float cn = fmaf(cz, cz, fmaf(cy, cy, __fmul_rn(cx, cx)));

    // thread t owns points n = j*256 + t  (coalesced, same pattern as smem version)
    uint32_t du[32];
    uint32_t bu = 0xffffffffu; int bi = t;
#pragma unroll 4
    for (int j = 0; j < 32; j++) {
        int n = j * 256 + t;
        float x = P[n*3+0], y = P[n*3+1], z = P[n*3+2];
        float pn  = fmaf(z, z, fmaf(y, y, __fmul_rn(x, x)));
        float dot = fmaf(cz, z, fmaf(cy, y, __fmul_rn(cx, x)));
        du[j] = ffold(__fadd_rn(cn, pn) - 2.0f * dot);
        if (du[j] < bu) { bu = du[j]; bi = n; }
    }

    for (int p = 0; p < NK; p++) {
        uint32_t vmin = __reduce_min_sync(0xffffffffu, bu);
        uint32_t cand = (bu == vmin) ? (uint32_t)bi : 0xffffffffu;
        uint32_t imin = __reduce_min_sync(0xffffffffu, cand);
        if (lane == 0) { rv[p & 1][wid] = vmin; ri[p & 1][wid] = imin; }
        __syncthreads();
        uint32_t v2 = (lane < 8) ? rv[p & 1][lane] : 0xffffffffu;
        uint32_t vm2 = __reduce_min_sync(0xffffffffu, v2);
        uint32_t c2  = (lane < 8 && v2 == vm2) ? ri[p & 1][lane] : 0xffffffffu;
        uint32_t fi  = __reduce_min_sync(0xffffffffu, c2);
        if (t == (int)(fi & 255u)) {
            sel[p] = (int)fi;
            int jf = (int)(fi >> 8);
#pragma unroll
            for (int j = 0; j < 32; j++)
                if (j == jf) du[j] = 0xffffffffu;
            bu = 0xffffffffu; bi = t;
#pragma unroll
            for (int j = 0; j < 32; j++)
                if (du[j] < bu) { bu = du[j]; bi = j * 256 + t; }
        }
    }
    __syncthreads();

    if (t < NK * 3) {
        int k = t / 3, c = t % 3;
        int n = sel[k];
        float cv = (c == 0) ? cx : (c == 1) ? cy : cz;
        PTS[t] = P[n*3+c] - cv;
    }
    __syncthreads();

    {
        int c  = t >> 1;
        int k0 = (t & 1) * 16;
        float wx = w1[c*3+0], wy = w1[c*3+1], wz = w1[c*3+2];
        float sc = bn1g[c] * rsqrtf(bn1v[c] + 1e-5f);
        float sh = fmaf(-bn1m[c], sc, bn1b[c]);
#pragma unroll
        for (int kk = 0; kk < 16; kk++) {
            int k = k0 + kk;
            float v = fmaf(PTS[k*3+2], wz, fmaf(PTS[k*3+1], wy, PTS[k*3+0] * wx));
            v = fmaxf(fmaf(v, sc, sh), 0.f);
            __half h, l; hsplit(v, h, l);
            size_t o = ((size_t)m * NK + k) * 128 + c;
            F1h[o] = h;
            F1l[o] = l;
        }
    }
}

// ===================== GEMM kernels (exact 1330µs configuration) =====================

__global__ __launch_bounds__(256, 2) void gemm2_kernel(const float* __restrict__ b2)
{
    int mtile = blockIdx.x >> 1, nt = blockIdx.x & 1;
    float acc[2][8][4] = {};
    gemm_core2(acc, F1h, F1l, W2q, mtile*128, nt*128, 128, 4);

    int t = threadIdx.x, lane = t & 31;
    int wm = (t >> 5) & 3, wn = t >> 7;
    int rb = wm*32 + (lane >> 2);
    int g  = mtile*4 + wm;
#pragma unroll
    for (int ni = 0; ni < 8; ni++) {
        int c = nt*128 + wn*64 + ni*8 + (lane & 3)*2;
        float bb0 = b2[c], bb1 = b2[c+1];
        float g0 = NEG_INF, g1 = NEG_INF;
#pragma unroll
        for (int mi = 0; mi < 2; mi++) {
            size_t row = (size_t)mtile*128 + rb + mi*16;
            float v0 = acc[mi][ni][0] + bb0, v1 = acc[mi][ni][1] + bb1;
            float v2 = acc[mi][ni][2] + bb0, v3 = acc[mi][ni][3] + bb1;
            *(uint32_t*)(F2q + row*256 + c)     = hpack2(v0, v1);
            *(uint32_t*)(F2q + (row+8)*256 + c) = hpack2(v2, v3);
            g0 = fmaxf(g0, fmaxf(v0, v2));
            g1 = fmaxf(g1, fmaxf(v1, v3));
        }
#pragma unroll
        for (int off = 4; off <= 16; off <<= 1) {
            g0 = fmaxf(g0, __shfl_xor_sync(0xffffffffu, g0, off));
            g1 = fmaxf(g1, __shfl_xor_sync(0xffffffffu, g1, off));
        }
        if (lane < 4)
            *(uint32_t*)(GMq + (size_t)g*256 + c) = hpack2(g0, g1);
    }
}

__global__ __launch_bounds__(256, 2) void gemm3g_kernel()
{
    int mtile = blockIdx.x >> 2, nt = blockIdx.x & 3;
    float acc[2][8][4] = {};
    gemm_core1(acc, GMq, W3gq, mtile*128, nt*128, 256, 4);

    int t = threadIdx.x, lane = t & 31;
    int wm = (t >> 5) & 3, wn = t >> 7;
    int rb = wm*32 + (lane >> 2);
#pragma unroll
    for (int ni = 0; ni < 8; ni++) {
        int c = nt*128 + wn*64 + ni*8 + (lane & 3)*2;
#pragma unroll
        for (int mi = 0; mi < 2; mi++) {
            size_t row = (size_t)mtile*128 + rb + mi*16;
            *(float2*)(G3 + row*512 + c)     = make_float2(acc[mi][ni][0], acc[mi][ni][1]);
            *(float2*)(G3 + (row+8)*512 + c) = make_float2(acc[mi][ni][2], acc[mi][ni][3]);
        }
    }
}

__global__ __launch_bounds__(256, 2) void gemm3f_kernel(
    const float* __restrict__ bn2g, const float* __restrict__ bn2b,
    const float* __restrict__ bn2m, const float* __restrict__ bn2v)
{
    int mtile = blockIdx.x >> 2, nt = blockIdx.x & 3;
    float acc[2][8][4] = {};
    gemm_core1(acc, F2q, W3fq, mtile*128, nt*128, 256, 4);

    extern __shared__ char smem[];
    float* sSC = (float*)smem;
    float* sSH = sSC + 128;
    float* sG  = sSH + 128;
    int t = threadIdx.x;
    if (t < 128) {
        int nl = nt*128 + t;
        float sc = bn2g[nl] * rsqrtf(bn2v[nl] + 1e-5f);
        sSC[t] = sc;
        sSH[t] = fmaf(-bn2m[nl], sc, bn2b[nl]);
    }
#pragma unroll
    for (int e = t; e < 512; e += 256)
        sG[e] = G3[(size_t)(mtile*4 + (e >> 7))*512 + nt*128 + (e & 127)];
    __syncthreads();

    int lane = t & 31;
    int wm = (t >> 5) & 3, wn = t >> 7;
    int rb = wm*32 + (lane >> 2);
#pragma unroll
    for (int ni = 0; ni < 8; ni++) {
        int lc = wn*64 + ni*8 + (lane & 3)*2;
        int c  = nt*128 + lc;
        float sc0 = sSC[lc], sc1 = sSC[lc+1];
        float sh0 = sSH[lc], sh1 = sSH[lc+1];
        float gv0 = sG[wm*128 + lc], gv1 = sG[wm*128 + lc + 1];
#pragma unroll
        for (int mi = 0; mi < 2; mi++) {
            size_t row = (size_t)mtile*128 + rb + mi*16;
            float v0 = fmaxf(fmaf(acc[mi][ni][0] + gv0, sc0, sh0), 0.f);
            float v1 = fmaxf(fmaf(acc[mi][ni][1] + gv1, sc1, sh1), 0.f);
            float v2 = fmaxf(fmaf(acc[mi][ni][2] + gv0, sc0, sh0), 0.f);
            float v3 = fmaxf(fmaf(acc[mi][ni][3] + gv1, sc1, sh1), 0.f);
            *(uint32_t*)(F3q + row*512 + c)     = hpack2(v0, v1);
            *(uint32_t*)(F3q + (row+8)*512 + c) = hpack2(v2, v3);
        }
    }
}

__global__ __launch_bounds__(256, 2) void gemm4_kernel(const float* __restrict__ b4,
                                                       float* __restrict__ tokens)
{
    int mtile = blockIdx.x / 3, nt = blockIdx.x % 3;
    float acc[2][8][4] = {};
    gemm_core1(acc, F3q, W4q, mtile*128, nt*128, 512, 8);

    int t = threadIdx.x, lane = t & 31;
    int wm = (t >> 5) & 3, wn = t >> 7;
    int g = mtile*4 + wm;
#pragma unroll
    for (int ni = 0; ni < 8; ni++) {
        int c = nt*128 + wn*64 + ni*8 + (lane & 3)*2;
        float bb0 = b4[c], bb1 = b4[c+1];
        float g0 = NEG_INF, g1 = NEG_INF;
#pragma unroll
        for (int mi = 0; mi < 2; mi++) {
            g0 = fmaxf(g0, fmaxf(acc[mi][ni][0], acc[mi][ni][2]));
            g1 = fmaxf(g1, fmaxf(acc[mi][ni][1], acc[mi][ni][3]));
        }
        g0 += bb0; g1 += bb1;
#pragma unroll
        for (int off = 4; off <= 16; off <<= 1) {
            g0 = fmaxf(g0, __shfl_xor_sync(0xffffffffu, g0, off));
            g1 = fmaxf(g1, __shfl_xor_sync(0xffffffffu, g1, off));
        }
        if (lane < 4)
            *(float2*)(tokens + (size_t)g*TOK + c) = make_float2(g0, g1);
    }
}

// =====================================================================
extern "C" void kernel_launch(void* const* d_in, const int* in_sizes, int n_in,
                              void* d_out, int out_size)
{
    const float* points = (const float*)d_in[0];
    const float* w1     = (const float*)d_in[1];
    const float* bn1g   = (const float*)d_in[2];
    const float* bn1b   = (const float*)d_in[3];
    const float* bn1m   = (const float*)d_in[4];
    const float* bn1v   = (const float*)d_in[5];
    const float* w2     = (const float*)d_in[6];
    const float* b2     = (const float*)d_in[7];
    const float* w3     = (const float*)d_in[8];
    const float* bn2g   = (const float*)d_in[9];
    const float* bn2b   = (const float*)d_in[10];
    const float* bn2m   = (const float*)d_in[11];
    const float* bn2v   = (const float*)d_in[12];
    const float* w4     = (const float*)d_in[13];
    const float* b4     = (const float*)d_in[14];

    float* tokens  = (float*)d_out;
    float* centers = (float*)d_out + (size_t)NM * TOK;

    static bool attr_done = false;
    if (!attr_done) {
        cudaFuncSetAttribute(fps_kernel,    cudaFuncAttributeMaxDynamicSharedMemorySize, NP*3*4);
        cudaFuncSetAttribute(gemm2_kernel,  cudaFuncAttributeMaxDynamicSharedMemorySize, GSMEM2);
        cudaFuncSetAttribute(gemm3g_kernel, cudaFuncAttributeMaxDynamicSharedMemorySize, GSMEM1);
        cudaFuncSetAttribute(gemm3f_kernel, cudaFuncAttributeMaxDynamicSharedMemorySize, GSMEM1);
        cudaFuncSetAttribute(gemm4_kernel,  cudaFuncAttributeMaxDynamicSharedMemorySize, GSMEM1);
        attr_done = true;
    }

    prep_kernel<<<256, 256>>>(w2, w3, w4);
    fps_kernel<<<NB, 1024, NP*3*4>>>(points, centers);
    group_kernel<<<NM, 256>>>(points, centers, w1, bn1g, bn1b, bn1m, bn1v);
    gemm2_kernel <<<4096, 256, GSMEM2>>>(b2);
    gemm3g_kernel<<<256,  256, GSMEM1>>>();
    gemm3f_kernel<<<8192, 256, GSMEM1>>>(bn2g, bn2b, bn2m, bn2v);
    gemm4_kernel <<<6144, 256, GSMEM1>>>(b4, tokens);
}

// round 17
// speedup vs baseline: 1.6137x; 1.0176x over previous
#include <cuda_runtime.h>
#include <cuda_fp16.h>
#include <cstdint>

#define NB 16
#define NP 8192
#define NG 512
#define NK 32
#define TOK 384
#define NM (NB*NG)          // 8192 groups
#define MTOT (NM*NK)        // 262144 rows

#define NEG_INF __int_as_float(0xff800000)

typedef unsigned long long ull;

// ===================== global scratch =====================
__device__ __align__(16) __half F1q[(size_t)MTOT*128];
__device__ __align__(16) __half F2q[(size_t)MTOT*256];
__device__ __align__(16) __half F3q[(size_t)MTOT*512];
__device__ __align__(16) __half GMq[(size_t)NM*256];
__device__ __align__(16) float  G3[(size_t)NM*512];
__device__ __align__(16) __half W2q[256*128];
__device__ __align__(16) __half W3gq[512*256];
__device__ __align__(16) __half W3fq[512*256];
__device__ __align__(16) __half W4q[384*512];

// ===================== helpers =====================
__device__ __forceinline__ uint32_t smem_u32(const void* p) {
    uint32_t a;
    asm("{ .reg .u64 t; cvta.to.shared.u64 t, %1; cvt.u32.u64 %0, t; }" : "=r"(a) : "l"(p));
    return a;
}
__device__ __forceinline__ uint32_t swz128(uint32_t o) { return o ^ ((o >> 3) & 0x70); }

__device__ __forceinline__ void cp16(uint32_t d, const void* s) {
    asm volatile("cp.async.cg.shared.global [%0], [%1], 16;" :: "r"(d), "l"(s));
}
__device__ __forceinline__ void ldsm4(uint32_t* r, uint32_t addr) {
    asm volatile("ldmatrix.sync.aligned.m8n8.x4.shared.b16 {%0,%1,%2,%3}, [%4];"
        : "=r"(r[0]), "=r"(r[1]), "=r"(r[2]), "=r"(r[3]) : "r"(addr));
}
__device__ __forceinline__ void mma16816(float* d, const uint32_t* a, const uint32_t* b) {
    asm volatile("mma.sync.aligned.m16n8k16.row.col.f32.f16.f16.f32 "
        "{%0,%1,%2,%3}, {%4,%5,%6,%7}, {%8,%9}, {%0,%1,%2,%3};"
        : "+f"(d[0]), "+f"(d[1]), "+f"(d[2]), "+f"(d[3])
        : "r"(a[0]), "r"(a[1]), "r"(a[2]), "r"(a[3]), "r"(b[0]), "r"(b[1]));
}
__device__ __forceinline__ uint32_t hpack2(float v0, float v1) {
    __half h0 = __float2half_rn(v0), h1 = __float2half_rn(v1);
    return (uint32_t)__half_as_ushort(h0) | ((uint32_t)__half_as_ushort(h1) << 16);
}
__device__ __forceinline__ uint32_t ffold(float x) {
    uint32_t b = __float_as_uint(x);
    return (b & 0x80000000u) ? ~b : (b | 0x80000000u);
}

// ============ core1: single-plane A & B, K-chunk 64, SW128, 3-stage, 256 thr ============
#define STG1 32768
#define GSMEM1 (3*32768)

__device__ __forceinline__ void load_chunk1(uint32_t base,
    const __half* __restrict__ A, const __half* __restrict__ B,
    int arow0, int brow0, int Kdim, int kc)
{
    int t = threadIdx.x;
#pragma unroll
    for (int it = 0; it < 8; it++) {
        int idx = t + it * 256;
        int arr = idx >> 10;
        int r   = (idx >> 3) & 127;
        int c   = idx & 7;
        uint32_t so = swz128((uint32_t)(r * 128 + c * 16));
        const __half* src = arr ? B : A;
        int row0 = arr ? brow0 : arow0;
        cp16(base + arr * 16384 + so, src + (size_t)(row0 + r) * Kdim + kc * 64 + c * 8);
    }
    asm volatile("cp.async.commit_group;" ::: "memory");
}
__device__ __forceinline__ void gemm_core1(float acc[2][8][4],
    const __half* __restrict__ A, const __half* __restrict__ B,
    int arow0, int brow0, int Kdim, int nchunk)
{
    extern __shared__ char smem[];
    uint32_t sb = smem_u32(smem);
    int t = threadIdx.x, lane = t & 31;
    int wm = (t >> 5) & 3, wn = t >> 7;
    uint32_t a_row = (uint32_t)(lane & 15);
    uint32_t a_kb  = (uint32_t)((lane >> 4) * 16);
    uint32_t b_row = (uint32_t)((lane & 7) + ((lane & 16) ? 8 : 0));
    uint32_t b_kb  = (uint32_t)(((lane >> 3) & 1) * 16);

    load_chunk1(sb,          A, B, arow0, brow0, Kdim, 0);
    if (nchunk > 1) load_chunk1(sb + STG1,   A, B, arow0, brow0, Kdim, 1);
    if (nchunk > 2) load_chunk1(sb + 2*STG1, A, B, arow0, brow0, Kdim, 2);

    for (int kc = 0; kc < nchunk; kc++) {
        int rem = nchunk - kc - 1;
        if (rem >= 2)      { asm volatile("cp.async.wait_group 2;" ::: "memory"); }
        else if (rem == 1) { asm volatile("cp.async.wait_group 1;" ::: "memory"); }
        else               { asm volatile("cp.async.wait_group 0;" ::: "memory"); }
        __syncthreads();
        uint32_t base = sb + (kc % 3) * STG1;
#pragma unroll
        for (int ks = 0; ks < 4; ks++) {
            uint32_t aH[2][4], bh[4][4];
#pragma unroll
            for (int mi = 0; mi < 2; mi++)
                ldsm4(aH[mi], base + swz128((uint32_t)((wm*32 + mi*16 + a_row)*128 + ks*32 + a_kb)));
#pragma unroll
            for (int np = 0; np < 4; np++)
                ldsm4(bh[np], base + 16384 + swz128((uint32_t)((wn*64 + np*16 + b_row)*128 + ks*32 + b_kb)));
#pragma unroll
            for (int mi = 0; mi < 2; mi++)
#pragma unroll
                for (int np = 0; np < 4; np++) {
                    mma16816(acc[mi][np*2],   aH[mi], bh[np]);
                    mma16816(acc[mi][np*2+1], aH[mi], bh[np] + 2);
                }
        }
        __syncthreads();
        if (kc + 3 < nchunk)
            load_chunk1(base, A, B, arow0, brow0, Kdim, kc + 3);
    }
}

// ===================== prep =====================
__global__ void prep_kernel(const float* __restrict__ w2, const float* __restrict__ w3,
                            const float* __restrict__ w4)
{
    int i = blockIdx.x * 256 + threadIdx.x;
    int stride = gridDim.x * 256;
    for (int j = i; j < 256*128; j += stride) W2q[j] = __float2half_rn(w2[j]);
    for (int j = i; j < 512*512; j += stride) {
        int n = j >> 9, k = j & 511;
        __half q = __float2half_rn(w3[j]);
        if (k < 256) W3gq[n*256 + k] = q;
        else         W3fq[n*256 + k - 256] = q;
    }
    for (int j = i; j < 384*512; j += stride) W4q[j] = __float2half_rn(w4[j]);
}

// ===================== FPS (bit-exact distances; cheaper argmax bookkeeping) =====================
__global__ __launch_bounds__(1024) void fps_kernel(
    const float* __restrict__ pts, float* __restrict__ centers)
{
    extern __shared__ float sp[];
    int b = blockIdx.x;
    int t = threadIdx.x;
    int lane = t & 31, wid = t >> 5;
    const float* P = pts + (size_t)b * NP * 3;

    for (int idx = t; idx < NP * 3; idx += 1024) sp[idx] = P[idx];
    __syncthreads();

    float px[8], py[8], pz[8], md[8];
#pragma unroll
    for (int j = 0; j < 8; j++) {
        int n = j * 1024 + t;
        px[j] = sp[n*3+0]; py[j] = sp[n*3+1]; pz[j] = sp[n*3+2];
        md[j] = 1e10f;
    }

    __shared__ uint32_t s_v[2][32];
    __shared__ uint32_t s_i[2][32];

    int last = 0;
    for (int s = 0; s < NG; s++) {
        float cx = sp[last*3+0], cy = sp[last*3+1], cz = sp[last*3+2];
        if (t == 0) {
            float* C = centers + ((size_t)b * NG + s) * 3;
            C[0] = cx; C[1] = cy; C[2] = cz;
        }

        // distance update: EXACT same math as before (selection-critical)
#pragma unroll
        for (int j = 0; j < 8; j++) {
            float dx = px[j] - cx, dy = py[j] - cy, dz = pz[j] - cz;
            float d2 = fmaf(dz, dz, fmaf(dy, dy, __fmul_rn(dx, dx)));
            md[j] = fminf(md[j], d2);
        }
        // tree max (values only)
        float m01 = fmaxf(md[0], md[1]), m23 = fmaxf(md[2], md[3]);
        float m45 = fmaxf(md[4], md[5]), m67 = fmaxf(md[6], md[7]);
        float bv = fmaxf(fmaxf(m01, m23), fmaxf(m45, m67));
        uint32_t bits = __float_as_uint(bv);
        uint32_t vmax = __reduce_max_sync(0xffffffffu, bits);
        // only max-holders scan for their lowest matching global index
        uint32_t cand = 0xffffffffu;
        if (bits == vmax) {
#pragma unroll
            for (int j = 7; j >= 0; j--)
                if (__float_as_uint(md[j]) == vmax) cand = (uint32_t)(j * 1024 + t);
        }
        uint32_t imin = __reduce_min_sync(0xffffffffu, cand);
        if (lane == 0) { s_v[s & 1][wid] = vmax; s_i[s & 1][wid] = imin; }
        __syncthreads();
        uint32_t v2 = s_v[s & 1][lane];
        uint32_t i2 = s_i[s & 1][lane];
        uint32_t vm2 = __reduce_max_sync(0xffffffffu, v2);
        uint32_t c2  = (v2 == vm2) ? i2 : 0xffffffffu;
        last = (int)__reduce_min_sync(0xffffffffu, c2);
    }
}

// ===================== grouping + stage1 (register top-K, coalesced; F1 single-plane) =====================
__global__ __launch_bounds__(256) void group_kernel(
    const float* __restrict__ pts, const float* __restrict__ centers,
    const float* __restrict__ w1,
    const float* __restrict__ bn1g, const float* __restrict__ bn1b,
    const float* __restrict__ bn1m, const float* __restrict__ bn1v)
{
    __shared__ uint32_t rv[2][8];
    __shared__ uint32_t ri[2][8];
    __shared__ int      sel[NK];
    __shared__ float    PTS[NK*3];

    int m = blockIdx.x;
    int b = m >> 9;
    int t = threadIdx.x;
    int lane = t & 31, wid = t >> 5;
    const float* P = pts + (size_t)b * NP * 3;

    float cx = centers[m*3+0], cy = centers[m*3+1], cz = centers[m*3+2];
    float cn = fmaf(cz, cz, fmaf(cy, cy, __fmul_rn(cx, cx)));

    uint32_t du[32];
    uint32_t bu = 0xffffffffu; int bi = t;
#pragma unroll 4
    for (int j = 0; j < 32; j++) {
        int n = j * 256 + t;
        float x = P[n*3+0], y = P[n*3+1], z = P[n*3+2];
        float pn  = fmaf(z, z, fmaf(y, y, __fmul_rn(x, x)));
        float dot = fmaf(cz, z, fmaf(cy, y, __fmul_rn(cx, x)));
        du[j] = ffold(__fadd_rn(cn, pn) - 2.0f * dot);
        if (du[j] < bu) { bu = du[j]; bi = n; }
    }

    for (int p = 0; p < NK; p++) {
        uint32_t vmin = __reduce_min_sync(0xffffffffu, bu);
        uint32_t cand = (bu == vmin) ? (uint32_t)bi : 0xffffffffu;
        uint32_t imin = __reduce_min_sync(0xffffffffu, cand);
        if (lane == 0) { rv[p & 1][wid] = vmin; ri[p & 1][wid] = imin; }
        __syncthreads();
        uint32_t v2 = (lane < 8) ? rv[p & 1][lane] : 0xffffffffu;
        uint32_t vm2 = __reduce_min_sync(0xffffffffu, v2);
        uint32_t c2  = (lane < 8 && v2 == vm2) ? ri[p & 1][lane] : 0xffffffffu;
        uint32_t fi  = __reduce_min_sync(0xffffffffu, c2);
        if (t == (int)(fi & 255u)) {
            sel[p] = (int)fi;
            int jf = (int)(fi >> 8);
#pragma unroll
            for (int j = 0; j < 32; j++)
                if (j == jf) du[j] = 0xffffffffu;
            bu = 0xffffffffu; bi = t;
#pragma unroll
            for (int j = 0; j < 32; j++)
                if (du[j] < bu) { bu = du[j]; bi = j * 256 + t; }
        }
    }
    __syncthreads();

    if (t < NK * 3) {
        int k = t / 3, c = t % 3;
        int n = sel[k];
        float cv = (c == 0) ? cx : (c == 1) ? cy : cz;
        PTS[t] = P[n*3+c] - cv;
    }
    __syncthreads();

    {
        int c  = t >> 1;
        int k0 = (t & 1) * 16;
        float wx = w1[c*3+0], wy = w1[c*3+1], wz = w1[c*3+2];
        float sc = bn1g[c] * rsqrtf(bn1v[c] + 1e-5f);
        float sh = fmaf(-bn1m[c], sc, bn1b[c]);
#pragma unroll
        for (int kk = 0; kk < 16; kk++) {
            int k = k0 + kk;
            float v = fmaf(PTS[k*3+2], wz, fmaf(PTS[k*3+1], wy, PTS[k*3+0] * wx));
            v = fmaxf(fmaf(v, sc, sh), 0.f);
            F1q[((size_t)m * NK + k) * 128 + c] = __float2half_rn(v);
        }
    }
}

// ===================== gemm2 (1-term, core1): F2 = F1 @ W2^T + b2 ; GM = group max =====================
__global__ __launch_bounds__(256, 2) void gemm2_kernel(const float* __restrict__ b2)
{
    int mtile = blockIdx.x >> 1, nt = blockIdx.x & 1;
    float acc[2][8][4] = {};
    gemm_core1(acc, F1q, W2q, mtile*128, nt*128, 128, 2);

    int t = threadIdx.x, lane = t & 31;
    int wm = (t >> 5) & 3, wn = t >> 7;
    int rb = wm*32 + (lane >> 2);
    int g  = mtile*4 + wm;
#pragma unroll
    for (int ni = 0; ni < 8; ni++) {
        int c = nt*128 + wn*64 + ni*8 + (lane & 3)*2;
        float bb0 = b2[c], bb1 = b2[c+1];
        float g0 = NEG_INF, g1 = NEG_INF;
#pragma unroll
        for (int mi = 0; mi < 2; mi++) {
            size_t row = (size_t)mtile*128 + rb + mi*16;
            float v0 = acc[mi][ni][0] + bb0, v1 = acc[mi][ni][1] + bb1;
            float v2 = acc[mi][ni][2] + bb0, v3 = acc[mi][ni][3] + bb1;
            *(uint32_t*)(F2q + row*256 + c)     = hpack2(v0, v1);
            *(uint32_t*)(F2q + (row+8)*256 + c) = hpack2(v2, v3);
            g0 = fmaxf(g0, fmaxf(v0, v2));
            g1 = fmaxf(g1, fmaxf(v1, v3));
        }
#pragma unroll
        for (int off = 4; off <= 16; off <<= 1) {
            g0 = fmaxf(g0, __shfl_xor_sync(0xffffffffu, g0, off));
            g1 = fmaxf(g1, __shfl_xor_sync(0xffffffffu, g1, off));
        }
        if (lane < 4)
            *(uint32_t*)(GMq + (size_t)g*256 + c) = hpack2(g0, g1);
    }
}

__global__ __launch_bounds__(256, 2) void gemm3g_kernel()
{
    int mtile = blockIdx.x >> 2, nt = blockIdx.x & 3;
    float acc[2][8][4] = {};
    gemm_core1(acc, GMq, W3gq, mtile*128, nt*128, 256, 4);

    int t = threadIdx.x, lane = t & 31;
    int wm = (t >> 5) & 3, wn = t >> 7;
    int rb = wm*32 + (lane >> 2);
#pragma unroll
    for (int ni = 0; ni < 8; ni++) {
        int c = nt*128 + wn*64 + ni*8 + (lane & 3)*2;
#pragma unroll
        for (int mi = 0; mi < 2; mi++) {
            size_t row = (size_t)mtile*128 + rb + mi*16;
            *(float2*)(G3 + row*512 + c)     = make_float2(acc[mi][ni][0], acc[mi][ni][1]);
            *(float2*)(G3 + (row+8)*512 + c) = make_float2(acc[mi][ni][2], acc[mi][ni][3]);
        }
    }
}

__global__ __launch_bounds__(256, 2) void gemm3f_kernel(
    const float* __restrict__ bn2g, const float* __restrict__ bn2b,
    const float* __restrict__ bn2m, const float* __restrict__ bn2v)
{
    int mtile = blockIdx.x >> 2, nt = blockIdx.x & 3;
    float acc[2][8][4] = {};
    gemm_core1(acc, F2q, W3fq, mtile*128, nt*128, 256, 4);

    extern __shared__ char smem[];
    float* sSC = (float*)smem;
    float* sSH = sSC + 128;
    float* sG  = sSH + 128;
    int t = threadIdx.x;
    if (t < 128) {
        int nl = nt*128 + t;
        float sc = bn2g[nl] * rsqrtf(bn2v[nl] + 1e-5f);
        sSC[t] = sc;
        sSH[t] = fmaf(-bn2m[nl], sc, bn2b[nl]);
    }
#pragma unroll
    for (int e = t; e < 512; e += 256)
        sG[e] = G3[(size_t)(mtile*4 + (e >> 7))*512 + nt*128 + (e & 127)];
    __syncthreads();

    int lane = t & 31;
    int wm = (t >> 5) & 3, wn = t >> 7;
    int rb = wm*32 + (lane >> 2);
#pragma unroll
    for (int ni = 0; ni < 8; ni++) {
        int lc = wn*64 + ni*8 + (lane & 3)*2;
        int c  = nt*128 + lc;
        float sc0 = sSC[lc], sc1 = sSC[lc+1];
        float sh0 = sSH[lc], sh1 = sSH[lc+1];
        float gv0 = sG[wm*128 + lc], gv1 = sG[wm*128 + lc + 1];
#pragma unroll
        for (int mi = 0; mi < 2; mi++) {
            size_t row = (size_t)mtile*128 + rb + mi*16;
            float v0 = fmaxf(fmaf(acc[mi][ni][0] + gv0, sc0, sh0), 0.f);
            float v1 = fmaxf(fmaf(acc[mi][ni][1] + gv1, sc1, sh1), 0.f);
            float v2 = fmaxf(fmaf(acc[mi][ni][2] + gv0, sc0, sh0), 0.f);
            float v3 = fmaxf(fmaf(acc[mi][ni][3] + gv1, sc1, sh1), 0.f);
            *(uint32_t*)(F3q + row*512 + c)     = hpack2(v0, v1);
            *(uint32_t*)(F3q + (row+8)*512 + c) = hpack2(v2, v3);
        }
    }
}

__global__ __launch_bounds__(256, 2) void gemm4_kernel(const float* __restrict__ b4,
                                                       float* __restrict__ tokens)
{
    int mtile = blockIdx.x / 3, nt = blockIdx.x % 3;
    float acc[2][8][4] = {};
    gemm_core1(acc, F3q, W4q, mtile*128, nt*128, 512, 8);

    int t = threadIdx.x, lane = t & 31;
    int wm = (t >> 5) & 3, wn = t >> 7;
    int g = mtile*4 + wm;
#pragma unroll
    for (int ni = 0; ni < 8; ni++) {
        int c = nt*128 + wn*64 + ni*8 + (lane & 3)*2;
        float bb0 = b4[c], bb1 = b4[c+1];
        float g0 = NEG_INF, g1 = NEG_INF;
#pragma unroll
        for (int mi = 0; mi < 2; mi++) {
            g0 = fmaxf(g0, fmaxf(acc[mi][ni][0], acc[mi][ni][2]));
            g1 = fmaxf(g1, fmaxf(acc[mi][ni][1], acc[mi][ni][3]));
        }
        g0 += bb0; g1 += bb1;
#pragma unroll
        for (int off = 4; off <= 16; off <<= 1) {
            g0 = fmaxf(g0, __shfl_xor_sync(0xffffffffu, g0, off));
            g1 = fmaxf(g1, __shfl_xor_sync(0xffffffffu, g1, off));
        }
        if (lane < 4)
            *(float2*)(tokens + (size_t)g*TOK + c) = make_float2(g0, g1);
    }
}

// =====================================================================
extern "C" void kernel_launch(void* const* d_in, const int* in_sizes, int n_in,
                              void* d_out, int out_size)
{
    const float* points = (const float*)d_in[0];
    const float* w1     = (const float*)d_in[1];
    const float* bn1g   = (const float*)d_in[2];
    const float* bn1b   = (const float*)d_in[3];
    const float* bn1m   = (const float*)d_in[4];
    const float* bn1v   = (const float*)d_in[5];
    const float* w2     = (const float*)d_in[6];
    const float* b2     = (const float*)d_in[7];
    const float* w3     = (const float*)d_in[8];
    const float* bn2g   = (const float*)d_in[9];
    const float* bn2b   = (const float*)d_in[10];
    const float* bn2m   = (const float*)d_in[11];
    const float* bn2v   = (const float*)d_in[12];
    const float* w4     = (const float*)d_in[13];
    const float* b4     = (const float*)d_in[14];

    float* tokens  = (float*)d_out;
    float* centers = (float*)d_out + (size_t)NM * TOK;

    static bool attr_done = false;
    if (!attr_done) {
        cudaFuncSetAttribute(fps_kernel,    cudaFuncAttributeMaxDynamicSharedMemorySize, NP*3*4);
        cudaFuncSetAttribute(gemm2_kernel,  cudaFuncAttributeMaxDynamicSharedMemorySize, GSMEM1);
        cudaFuncSetAttribute(gemm3g_kernel, cudaFuncAttributeMaxDynamicSharedMemorySize, GSMEM1);
        cudaFuncSetAttribute(gemm3f_kernel, cudaFuncAttributeMaxDynamicSharedMemorySize, GSMEM1);
        cudaFuncSetAttribute(gemm4_kernel,  cudaFuncAttributeMaxDynamicSharedMemorySize, GSMEM1);
        attr_done = true;
    }

    prep_kernel<<<256, 256>>>(w2, w3, w4);
    fps_kernel<<<NB, 1024, NP*3*4>>>(points, centers);
    group_kernel<<<NM, 256>>>(points, centers, w1, bn1g, bn1b, bn1m, bn1v);
    gemm2_kernel <<<4096, 256, GSMEM1>>>(b2);
    gemm3g_kernel<<<256,  256, GSMEM1>>>();
    gemm3f_kernel<<<8192, 256, GSMEM1>>>(bn2g, bn2b, bn2m, bn2v);
    gemm4_kernel <<<6144, 256, GSMEM1>>>(b4, tokens);
}